// round 4
// baseline (speedup 1.0000x reference)
#include <cuda_runtime.h>
#include <math.h>
#include <stdint.h>

// Problem dims
constexpr int BB = 32;
constexpr int LL = 256;
constexpr int SS = 64;
constexpr int TT = 64;
constexpr int QD = 768;
constexpr int FD = 1024;
constexpr int HD = 768;
constexpr int OD = 768;
constexpr int TSD = TT * SS;
constexpr int XD = QD + HD;

// Scratch
__device__ __align__(16) float g_q[(size_t)BB * LL * HD];
__device__ __align__(16) float g_skey[(size_t)BB * SS * HD];
__device__ __align__(16) float g_tkey[(size_t)BB * TT * HD];
__device__ __align__(16) float g_rel[(size_t)BB * TSD * HD];
__device__ __align__(16) float g_scores[(size_t)BB * LL * TSD];
__device__ __align__(16) float g_x[(size_t)BB * LL * XD];

__device__ __forceinline__ float f2tf32f(float f) {
    uint32_t r;
    asm("cvt.rna.tf32.f32 %0, %1;" : "=r"(r) : "f"(f));
    return __uint_as_float(r);
}

__device__ __forceinline__ void mma8(float* c, const uint32_t* a,
                                     uint32_t b0, uint32_t b1) {
    asm volatile(
        "mma.sync.aligned.m16n8k8.row.col.f32.tf32.tf32.f32 "
        "{%0,%1,%2,%3}, {%4,%5,%6,%7}, {%8,%9}, {%0,%1,%2,%3};"
        : "+f"(c[0]), "+f"(c[1]), "+f"(c[2]), "+f"(c[3])
        : "r"(a[0]), "r"(a[1]), "r"(a[2]), "r"(a[3]), "r"(b0), "r"(b1));
}

// ---------------------------------------------------------------------------
// TF32 tensor-core GEMM, double-buffered, crosswise A fragments.
//   NT=false: C = act(scale * A(MxK) @ B(KxN) + bias)
//   NT=true : C = act(scale * A(MxK) @ B(NxK)^T + bias)
// Block 128x128, BK=16, 256 threads (8 warps 2m x 4n), warp tile 64x32.
// A smem layout (per buffer): for element (m,k), k<16:
//   arow = (m>>4)*8 + (m&7); h_m=(m>>3)&1; blk=(k>>3); g=(k&3); h_k=(k>>2)&1
//   addr = (arow*32 + blk*16 + g*4 + h_k*2 + h_m) ^ ((arow&1)<<4)
// -> one LDS.128 per 4-value A fragment, conflict-free reads.
// B NT: [n][k] stride 20 (banks (20q+r) mod 32 distinct).
// B NN: [k][n] stride 136 (as before, conflict-free frag reads).
// ---------------------------------------------------------------------------
template <bool NT>
__global__ __launch_bounds__(256) void mma_gemm(
    const float* __restrict__ A, int lda, size_t sA_,
    const float* __restrict__ B, int ldb, size_t sB_,
    const float* __restrict__ bias,
    float* __restrict__ C, int ldc, size_t sC_,
    int K, float scale, int do_relu)
{
    __shared__ float sA[2][64 * 32];                       // 16 KB
    __shared__ float sB[2][NT ? (128 * 20) : (16 * 136)];  // 20 / 17.4 KB

    const float* Ab = A + blockIdx.z * sA_;
    const float* Bb = B + blockIdx.z * sB_;
    float* Cb = C + blockIdx.z * sC_;

    const int tid  = threadIdx.x;
    const int lane = tid & 31;
    const int wid  = tid >> 5;
    const int wm   = wid & 1;
    const int wn   = wid >> 1;
    const int bm   = blockIdx.y * 128;
    const int bn   = blockIdx.x * 128;

    // Loader indices
    const int la_m  = tid >> 2;            // 0..63 (+64)
    const int la_c4 = (tid & 3) * 4;       // 0,4,8,12
    const int lb_r  = tid >> 5;            // NN: 0..7 (+8)
    const int lb_c4 = (tid & 31) * 4;      // NN: 0..124

    float4 ra[2], rb[2];

    auto ldgA = [&](int k0) {
#pragma unroll
        for (int i = 0; i < 2; i++)
            ra[i] = *(const float4*)(Ab + (size_t)(bm + la_m + 64 * i) * lda + k0 + la_c4);
    };
    auto stsA = [&](int p) {
#pragma unroll
        for (int i = 0; i < 2; i++) {
            int m = la_m + 64 * i;
            int arow = ((m >> 4) << 3) | (m & 7);
            int hm = (m >> 3) & 1;
            int blk = la_c4 >> 3;
            int hk = (la_c4 >> 2) & 1;
            int base = arow * 32 + (blk << 4) + (hk << 1) + hm;
            int sw = (arow & 1) << 4;
            sA[p][(base + 0) ^ sw]  = f2tf32f(ra[i].x);
            sA[p][(base + 4) ^ sw]  = f2tf32f(ra[i].y);
            sA[p][(base + 8) ^ sw]  = f2tf32f(ra[i].z);
            sA[p][(base + 12) ^ sw] = f2tf32f(ra[i].w);
        }
    };
    auto ldgB = [&](int k0) {
        if (NT) {
#pragma unroll
            for (int i = 0; i < 2; i++)
                rb[i] = *(const float4*)(Bb + (size_t)(bn + la_m + 64 * i) * ldb + k0 + la_c4);
        } else {
#pragma unroll
            for (int i = 0; i < 2; i++)
                rb[i] = *(const float4*)(Bb + (size_t)(k0 + lb_r + 8 * i) * ldb + bn + lb_c4);
        }
    };
    auto stsB = [&](int p) {
        if (NT) {
#pragma unroll
            for (int i = 0; i < 2; i++) {
                int n = la_m + 64 * i;
                int off = n * 20 + la_c4;
                sB[p][off + 0] = f2tf32f(rb[i].x);
                sB[p][off + 1] = f2tf32f(rb[i].y);
                sB[p][off + 2] = f2tf32f(rb[i].z);
                sB[p][off + 3] = f2tf32f(rb[i].w);
            }
        } else {
#pragma unroll
            for (int i = 0; i < 2; i++) {
                float4 v;
                v.x = f2tf32f(rb[i].x); v.y = f2tf32f(rb[i].y);
                v.z = f2tf32f(rb[i].z); v.w = f2tf32f(rb[i].w);
                *(float4*)&sB[p][(lb_r + 8 * i) * 136 + lb_c4] = v;
            }
        }
    };

    float acc[4][4][4] = {};

    auto compute = [&](int p) {
#pragma unroll
        for (int kk = 0; kk < 2; kk++) {
            const int kb = kk * 8;
            uint4 a[4];
#pragma unroll
            for (int mt = 0; mt < 4; mt++) {
                int arow = (wm * 4 + mt) * 8 + (lane >> 2);
                int addr = (arow * 32 + (kk << 4) + ((lane & 3) << 2)) ^ ((arow & 1) << 4);
                a[mt] = *(const uint4*)(&sA[p][addr]);
            }
#pragma unroll
            for (int nt = 0; nt < 4; nt++) {
                int n0 = wn * 32 + nt * 8 + (lane >> 2);
                uint32_t b0, b1;
                if (NT) {
                    int off = n0 * 20 + kb + (lane & 3);
                    b0 = __float_as_uint(sB[p][off]);
                    b1 = __float_as_uint(sB[p][off + 4]);
                } else {
                    int kr = kb + (lane & 3);
                    b0 = __float_as_uint(sB[p][kr * 136 + n0]);
                    b1 = __float_as_uint(sB[p][(kr + 4) * 136 + n0]);
                }
#pragma unroll
                for (int mt = 0; mt < 4; mt++)
                    mma8(acc[mt][nt], (const uint32_t*)&a[mt], b0, b1);
            }
        }
    };

    // Prologue
    ldgA(0); ldgB(0);
    stsA(0); stsB(0);
    __syncthreads();

    int p = 0;
    for (int k0 = 16; k0 <= K; k0 += 16) {
        bool more = (k0 < K);
        if (more) { ldgA(k0); ldgB(k0); }
        compute(p);
        if (more) {
            stsA(p ^ 1); stsB(p ^ 1);
            __syncthreads();
            p ^= 1;
        }
    }

    // Epilogue
#pragma unroll
    for (int nt = 0; nt < 4; nt++) {
        int col = bn + wn * 32 + nt * 8 + (lane & 3) * 2;
        float bv0 = 0.f, bv1 = 0.f;
        if (bias) { bv0 = bias[col]; bv1 = bias[col + 1]; }
#pragma unroll
        for (int mt = 0; mt < 4; mt++) {
            int r0 = bm + wm * 64 + mt * 16 + (lane >> 2);
            float v0 = acc[mt][nt][0] * scale + bv0;
            float v1 = acc[mt][nt][1] * scale + bv1;
            float v2 = acc[mt][nt][2] * scale + bv0;
            float v3 = acc[mt][nt][3] * scale + bv1;
            if (do_relu) {
                v0 = fmaxf(v0, 0.f); v1 = fmaxf(v1, 0.f);
                v2 = fmaxf(v2, 0.f); v3 = fmaxf(v3, 0.f);
            }
            *(float2*)(Cb + (size_t)r0 * ldc + col) = make_float2(v0, v1);
            *(float2*)(Cb + (size_t)(r0 + 8) * ldc + col) = make_float2(v2, v3);
        }
    }
}

// ---------------------------------------------------------------------------
__global__ __launch_bounds__(256) void relkey_kernel(
    const float* __restrict__ skey, const float* __restrict__ tkey,
    float* __restrict__ rel)
{
    const size_t H4 = HD / 4;
    size_t idx = (size_t)blockIdx.x * blockDim.x + threadIdx.x;
    size_t h4 = idx % H4;
    size_t rest = idx / H4;
    int s = (int)(rest % SS); rest /= SS;
    int t = (int)(rest % TT);
    int b = (int)(rest / TT);
    float4 sv = ((const float4*)skey)[((size_t)b * SS + s) * H4 + h4];
    float4 tv = ((const float4*)tkey)[((size_t)b * TT + t) * H4 + h4];
    float4 o;
    o.x = tanhf(sv.x + tv.x);
    o.y = tanhf(sv.y + tv.y);
    o.z = tanhf(sv.z + tv.z);
    o.w = tanhf(sv.w + tv.w);
    ((float4*)rel)[idx] = o;
}

__global__ __launch_bounds__(256) void softmax_kernel(float* __restrict__ data)
{
    float* row = data + (size_t)blockIdx.x * TSD;
    const int tid = threadIdx.x;
    float v[16];
    float m = -INFINITY;
#pragma unroll
    for (int i = 0; i < 16; i++) {
        v[i] = row[tid + i * 256];
        m = fmaxf(m, v[i]);
    }
#pragma unroll
    for (int o = 16; o; o >>= 1) m = fmaxf(m, __shfl_xor_sync(0xffffffffu, m, o));
    __shared__ float redm[8];
    __shared__ float reds[8];
    if ((tid & 31) == 0) redm[tid >> 5] = m;
    __syncthreads();
#pragma unroll
    for (int w = 0; w < 8; w++) m = fmaxf(m, redm[w]);
    float s = 0.f;
#pragma unroll
    for (int i = 0; i < 16; i++) {
        v[i] = expf(v[i] - m);
        s += v[i];
    }
#pragma unroll
    for (int o = 16; o; o >>= 1) s += __shfl_xor_sync(0xffffffffu, s, o);
    if ((tid & 31) == 0) reds[tid >> 5] = s;
    __syncthreads();
    s = 0.f;
#pragma unroll
    for (int w = 0; w < 8; w++) s += reds[w];
    float inv = 1.f / s;
#pragma unroll
    for (int i = 0; i < 16; i++) row[tid + i * 256] = v[i] * inv;
}

__global__ __launch_bounds__(256) void concat_kernel(
    const float* __restrict__ q, float* __restrict__ x)
{
    const size_t Q4 = QD / 4;
    size_t idx = (size_t)blockIdx.x * blockDim.x + threadIdx.x;
    size_t rowi = idx / Q4;
    size_t c4 = idx % Q4;
    ((float4*)x)[rowi * (XD / 4) + c4] = ((const float4*)q)[idx];
}

// ---------------------------------------------------------------------------
extern "C" void kernel_launch(void* const* d_in, const int* in_sizes, int n_in,
                              void* d_out, int out_size)
{
    const float* query = (const float*)d_in[0];
    const float* src   = (const float*)d_in[1];
    const float* trg   = (const float*)d_in[2];
    const float* Wq    = (const float*)d_in[3];
    const float* b_q   = (const float*)d_in[4];
    const float* Ws    = (const float*)d_in[5];
    const float* b_s   = (const float*)d_in[6];
    const float* Wt    = (const float*)d_in[7];
    const float* b_t   = (const float*)d_in[8];
    const float* Wo    = (const float*)d_in[9];
    const float* b_o   = (const float*)d_in[10];
    float* out = (float*)d_out;

    float *q, *skey, *tkey, *rel, *scores, *x;
    cudaGetSymbolAddress((void**)&q, g_q);
    cudaGetSymbolAddress((void**)&skey, g_skey);
    cudaGetSymbolAddress((void**)&tkey, g_tkey);
    cudaGetSymbolAddress((void**)&rel, g_rel);
    cudaGetSymbolAddress((void**)&scores, g_scores);
    cudaGetSymbolAddress((void**)&x, g_x);

    const float inv_sqrt_h = 1.0f / sqrtf((float)HD);
    dim3 blk(256);

    // 1. q = query @ Wq + b_q
    mma_gemm<false><<<dim3(HD / 128, (BB * LL) / 128, 1), blk>>>(
        query, QD, 0, Wq, HD, 0, b_q, q, HD, 0, QD, 1.f, 0);

    // 2. s_key = src @ Ws + b_s
    mma_gemm<false><<<dim3(HD / 128, (BB * SS) / 128, 1), blk>>>(
        src, FD, 0, Ws, HD, 0, b_s, skey, HD, 0, FD, 1.f, 0);

    // 3. t_key = trg @ Wt + b_t
    mma_gemm<false><<<dim3(HD / 128, (BB * TT) / 128, 1), blk>>>(
        trg, FD, 0, Wt, HD, 0, b_t, tkey, HD, 0, FD, 1.f, 0);

    // 4. rel_key = tanh(s_key + t_key)
    {
        size_t n4 = (size_t)BB * TSD * HD / 4;
        relkey_kernel<<<(unsigned)(n4 / 256), blk>>>(skey, tkey, rel);
    }

    // 5. scores = q . rel^T / sqrt(H)
    mma_gemm<true><<<dim3(TSD / 128, LL / 128, BB), blk>>>(
        q, HD, (size_t)LL * HD,
        rel, HD, (size_t)TSD * HD,
        nullptr,
        scores, TSD, (size_t)LL * TSD,
        HD, inv_sqrt_h, 0);

    // 6. softmax
    softmax_kernel<<<BB * LL, blk>>>(scores);

    // 7. x[:, :768] = query
    {
        size_t n4 = (size_t)BB * LL * QD / 4;
        concat_kernel<<<(unsigned)(n4 / 256), blk>>>(query, x);
    }

    // 8. x[:, 768:] = scores @ rel
    mma_gemm<false><<<dim3(HD / 128, LL / 128, BB), blk>>>(
        scores, TSD, (size_t)LL * TSD,
        rel, HD, (size_t)TSD * HD,
        nullptr,
        x + QD, XD, (size_t)LL * XD,
        TSD, 1.f, 0);

    // 9. out = relu(x @ Wo + b_o)
    mma_gemm<false><<<dim3(OD / 128, (BB * LL) / 128, 1), blk>>>(
        x, XD, 0, Wo, OD, 0, b_o, out, OD, 0, XD, 1.f, 1);
}

// round 5
// speedup vs baseline: 1.6093x; 1.6093x over previous
#include <cuda_runtime.h>
#include <math.h>
#include <stdint.h>

// Problem dims
constexpr int BB = 32;
constexpr int LL = 256;
constexpr int SS = 64;
constexpr int TT = 64;
constexpr int QD = 768;
constexpr int FD = 1024;
constexpr int HD = 768;
constexpr int OD = 768;
constexpr int TSD = TT * SS;
constexpr int XD = QD + HD;

// Scratch (static device globals)
__device__ __align__(16) float g_q[(size_t)BB * LL * HD];
__device__ __align__(16) float g_skey[(size_t)BB * SS * HD];
__device__ __align__(16) float g_tkey[(size_t)BB * TT * HD];
__device__ __align__(16) float g_rel[(size_t)BB * TSD * HD];
__device__ __align__(16) float g_scores[(size_t)BB * LL * TSD];
__device__ __align__(16) float g_x[(size_t)BB * LL * XD];
// tf32-pre-rounded copies of raw inputs / weights
__device__ __align__(16) float g_qin[(size_t)BB * LL * QD];
__device__ __align__(16) float g_srcc[(size_t)BB * SS * FD];
__device__ __align__(16) float g_trgc[(size_t)BB * TT * FD];
__device__ __align__(16) float g_wq[(size_t)QD * HD];
__device__ __align__(16) float g_ws[(size_t)FD * HD];
__device__ __align__(16) float g_wt[(size_t)FD * HD];
__device__ __align__(16) float g_wo[(size_t)XD * OD];

__device__ __forceinline__ float f2tf32f(float f) {
    uint32_t r;
    asm("cvt.rna.tf32.f32 %0, %1;" : "=r"(r) : "f"(f));
    return __uint_as_float(r);
}

__device__ __forceinline__ void mma8(float* c, const uint32_t* a,
                                     uint32_t b0, uint32_t b1) {
    asm volatile(
        "mma.sync.aligned.m16n8k8.row.col.f32.tf32.tf32.f32 "
        "{%0,%1,%2,%3}, {%4,%5,%6,%7}, {%8,%9}, {%0,%1,%2,%3};"
        : "+f"(c[0]), "+f"(c[1]), "+f"(c[2]), "+f"(c[3])
        : "r"(a[0]), "r"(a[1]), "r"(a[2]), "r"(a[3]), "r"(b0), "r"(b1));
}

__device__ __forceinline__ void cp16(uint32_t dst_smem, const float* src) {
    asm volatile("cp.async.cg.shared.global [%0], [%1], 16;\n"
                 :: "r"(dst_smem), "l"(src));
}
__device__ __forceinline__ void cp_commit() {
    asm volatile("cp.async.commit_group;\n");
}
template <int N>
__device__ __forceinline__ void cp_wait() {
    asm volatile("cp.async.wait_group %0;\n" :: "n"(N));
}

// ---------------------------------------------------------------------------
// TF32 tensor-core GEMM, cp.async 2-stage double buffer.
// Inputs must already be tf32-rounded in memory.
//   NT=false: C = act(scale * A(MxK) @ B(KxN) + bias)
//   NT=true : C = act(scale * A(MxK) @ B(NxK)^T + bias)
// Block 128x128, BK=32, 256 threads (8 warps 2m x 4n), warp tile 64x32.
// Smem (dynamic): [A stage0][A stage1][B stage0][B stage1]
//   A / NT-B: 128 rows x stride 36 (conflict-free frag reads, verified R2)
//   NN-B:     32 rows x stride 136
// ---------------------------------------------------------------------------
constexpr int A_STG = 128 * 36;   // floats per A stage
constexpr int BNT_STG = 128 * 36;
constexpr int BNN_STG = 32 * 136;

template <bool NT>
__global__ __launch_bounds__(256) void mma_gemm(
    const float* __restrict__ A, int lda, size_t sA_,
    const float* __restrict__ B, int ldb, size_t sB_,
    const float* __restrict__ bias,
    float* __restrict__ C, int ldc, size_t sC_,
    int K, float scale, int do_relu, int cvt_out)
{
    extern __shared__ float sm[];
    float* sAbase = sm;
    float* sBbase = sm + 2 * A_STG;
    constexpr int BSTG = NT ? BNT_STG : BNN_STG;

    const float* Ab = A + blockIdx.z * sA_;
    const float* Bb = B + blockIdx.z * sB_;
    float* Cb = C + blockIdx.z * sC_;

    const int tid  = threadIdx.x;
    const int lane = tid & 31;
    const int wid  = tid >> 5;
    const int wm   = wid & 1;
    const int wn   = wid >> 1;
    const int bm   = blockIdx.y * 128;
    const int bn   = blockIdx.x * 128;

    // A loader: 1024 16B-chunks, 4/thread: row r=(tid>>3)+32i, col c4=(tid&7)*4
    const int la_r  = tid >> 3;
    const int la_c4 = (tid & 7) * 4;
    // NN B loader: row r=(tid>>5)+8i, col c4=(tid&31)*4
    const int lbn_r  = tid >> 5;
    const int lbn_c4 = (tid & 31) * 4;

    uint32_t sA_u = (uint32_t)__cvta_generic_to_shared(sAbase);
    uint32_t sB_u = (uint32_t)__cvta_generic_to_shared(sBbase);

    auto issue = [&](int p, int k0) {
        uint32_t ap = sA_u + (p * A_STG) * 4;
#pragma unroll
        for (int i = 0; i < 4; i++) {
            int r = la_r + 32 * i;
            cp16(ap + (r * 36 + la_c4) * 4,
                 Ab + (size_t)(bm + r) * lda + k0 + la_c4);
        }
        uint32_t bp = sB_u + (p * BSTG) * 4;
        if (NT) {
#pragma unroll
            for (int i = 0; i < 4; i++) {
                int r = la_r + 32 * i;
                cp16(bp + (r * 36 + la_c4) * 4,
                     Bb + (size_t)(bn + r) * ldb + k0 + la_c4);
            }
        } else {
#pragma unroll
            for (int i = 0; i < 4; i++) {
                int r = lbn_r + 8 * i;
                cp16(bp + (r * 136 + lbn_c4) * 4,
                     Bb + (size_t)(k0 + r) * ldb + bn + lbn_c4);
            }
        }
    };

    float acc[4][4][4] = {};

    auto compute = [&](int p) {
        const float* sAs = sAbase + p * A_STG;
        const float* sBs = sBbase + p * BSTG;
#pragma unroll
        for (int kk = 0; kk < 4; kk++) {
            const int kb = kk * 8;
            uint32_t a[4][4];
#pragma unroll
            for (int mt = 0; mt < 4; mt++) {
                int m0 = wm * 64 + mt * 16 + (lane >> 2);
                int kc = kb + (lane & 3);
                a[mt][0] = __float_as_uint(sAs[m0 * 36 + kc]);
                a[mt][1] = __float_as_uint(sAs[(m0 + 8) * 36 + kc]);
                a[mt][2] = __float_as_uint(sAs[m0 * 36 + kc + 4]);
                a[mt][3] = __float_as_uint(sAs[(m0 + 8) * 36 + kc + 4]);
            }
#pragma unroll
            for (int nt = 0; nt < 4; nt++) {
                int n0 = wn * 32 + nt * 8 + (lane >> 2);
                uint32_t b0, b1;
                if (NT) {
                    int off = n0 * 36 + kb + (lane & 3);
                    b0 = __float_as_uint(sBs[off]);
                    b1 = __float_as_uint(sBs[off + 4]);
                } else {
                    int kr = kb + (lane & 3);
                    b0 = __float_as_uint(sBs[kr * 136 + n0]);
                    b1 = __float_as_uint(sBs[(kr + 4) * 136 + n0]);
                }
#pragma unroll
                for (int mt = 0; mt < 4; mt++)
                    mma8(acc[mt][nt], a[mt][0] ? a[mt] : a[mt], b0, b1);
            }
        }
    };

    const int NI = K / 32;
    issue(0, 0);
    cp_commit();

    for (int it = 0; it < NI; it++) {
        if (it + 1 < NI) {
            issue((it + 1) & 1, (it + 1) * 32);
            cp_commit();
            cp_wait<1>();
        } else {
            cp_wait<0>();
        }
        __syncthreads();
        compute(it & 1);
        __syncthreads();
    }

    // Epilogue
#pragma unroll
    for (int nt = 0; nt < 4; nt++) {
        int col = bn + wn * 32 + nt * 8 + (lane & 3) * 2;
        float bv0 = 0.f, bv1 = 0.f;
        if (bias) { bv0 = bias[col]; bv1 = bias[col + 1]; }
#pragma unroll
        for (int mt = 0; mt < 4; mt++) {
            int r0 = bm + wm * 64 + mt * 16 + (lane >> 2);
            float v0 = acc[mt][nt][0] * scale + bv0;
            float v1 = acc[mt][nt][1] * scale + bv1;
            float v2 = acc[mt][nt][2] * scale + bv0;
            float v3 = acc[mt][nt][3] * scale + bv1;
            if (do_relu) {
                v0 = fmaxf(v0, 0.f); v1 = fmaxf(v1, 0.f);
                v2 = fmaxf(v2, 0.f); v3 = fmaxf(v3, 0.f);
            }
            if (cvt_out) {
                v0 = f2tf32f(v0); v1 = f2tf32f(v1);
                v2 = f2tf32f(v2); v3 = f2tf32f(v3);
            }
            *(float2*)(Cb + (size_t)r0 * ldc + col) = make_float2(v0, v1);
            *(float2*)(Cb + (size_t)(r0 + 8) * ldc + col) = make_float2(v2, v3);
        }
    }
}

// ---------------------------------------------------------------------------
// Elementwise tf32 pre-round: y[i] = tf32(x[i])
__global__ __launch_bounds__(256) void cvt_tf32_kernel(
    const float* __restrict__ x, float* __restrict__ y)
{
    size_t i = (size_t)blockIdx.x * blockDim.x + threadIdx.x;
    float4 v = ((const float4*)x)[i];
    v.x = f2tf32f(v.x); v.y = f2tf32f(v.y);
    v.z = f2tf32f(v.z); v.w = f2tf32f(v.w);
    ((float4*)y)[i] = v;
}

// rel_key[b,t,s,h] = tf32(tanh(s_key[b,s,h] + t_key[b,t,h]))
__global__ __launch_bounds__(256) void relkey_kernel(
    const float* __restrict__ skey, const float* __restrict__ tkey,
    float* __restrict__ rel)
{
    const size_t H4 = HD / 4;
    size_t idx = (size_t)blockIdx.x * blockDim.x + threadIdx.x;
    size_t h4 = idx % H4;
    size_t rest = idx / H4;
    int s = (int)(rest % SS); rest /= SS;
    int t = (int)(rest % TT);
    int b = (int)(rest / TT);
    float4 sv = ((const float4*)skey)[((size_t)b * SS + s) * H4 + h4];
    float4 tv = ((const float4*)tkey)[((size_t)b * TT + t) * H4 + h4];
    float4 o;
    o.x = f2tf32f(tanhf(sv.x + tv.x));
    o.y = f2tf32f(tanhf(sv.y + tv.y));
    o.z = f2tf32f(tanhf(sv.z + tv.z));
    o.w = f2tf32f(tanhf(sv.w + tv.w));
    ((float4*)rel)[idx] = o;
}

// Softmax over 4096 per row; output tf32-rounded (feeds GEMM 8).
__global__ __launch_bounds__(256) void softmax_kernel(float* __restrict__ data)
{
    float* row = data + (size_t)blockIdx.x * TSD;
    const int tid = threadIdx.x;
    float v[16];
    float m = -INFINITY;
#pragma unroll
    for (int i = 0; i < 16; i++) {
        v[i] = row[tid + i * 256];
        m = fmaxf(m, v[i]);
    }
#pragma unroll
    for (int o = 16; o; o >>= 1) m = fmaxf(m, __shfl_xor_sync(0xffffffffu, m, o));
    __shared__ float redm[8];
    __shared__ float reds[8];
    if ((tid & 31) == 0) redm[tid >> 5] = m;
    __syncthreads();
#pragma unroll
    for (int w = 0; w < 8; w++) m = fmaxf(m, redm[w]);
    float s = 0.f;
#pragma unroll
    for (int i = 0; i < 16; i++) {
        v[i] = expf(v[i] - m);
        s += v[i];
    }
#pragma unroll
    for (int o = 16; o; o >>= 1) s += __shfl_xor_sync(0xffffffffu, s, o);
    if ((tid & 31) == 0) reds[tid >> 5] = s;
    __syncthreads();
    s = 0.f;
#pragma unroll
    for (int w = 0; w < 8; w++) s += reds[w];
    float inv = 1.f / s;
#pragma unroll
    for (int i = 0; i < 16; i++) row[tid + i * 256] = f2tf32f(v[i] * inv);
}

// x[:, :768] = tf32(query)
__global__ __launch_bounds__(256) void concat_kernel(
    const float* __restrict__ q, float* __restrict__ x)
{
    const size_t Q4 = QD / 4;
    size_t idx = (size_t)blockIdx.x * blockDim.x + threadIdx.x;
    size_t rowi = idx / Q4;
    size_t c4 = idx % Q4;
    float4 v = ((const float4*)q)[idx];
    v.x = f2tf32f(v.x); v.y = f2tf32f(v.y);
    v.z = f2tf32f(v.z); v.w = f2tf32f(v.w);
    ((float4*)x)[rowi * (XD / 4) + c4] = v;
}

// ---------------------------------------------------------------------------
extern "C" void kernel_launch(void* const* d_in, const int* in_sizes, int n_in,
                              void* d_out, int out_size)
{
    const float* query = (const float*)d_in[0];
    const float* src   = (const float*)d_in[1];
    const float* trg   = (const float*)d_in[2];
    const float* Wq    = (const float*)d_in[3];
    const float* b_q   = (const float*)d_in[4];
    const float* Ws    = (const float*)d_in[5];
    const float* b_s   = (const float*)d_in[6];
    const float* Wt    = (const float*)d_in[7];
    const float* b_t   = (const float*)d_in[8];
    const float* Wo    = (const float*)d_in[9];
    const float* b_o   = (const float*)d_in[10];
    float* out = (float*)d_out;

    float *q, *skey, *tkey, *rel, *scores, *x;
    float *qin, *srcc, *trgc, *wq, *ws, *wt, *wo;
    cudaGetSymbolAddress((void**)&q, g_q);
    cudaGetSymbolAddress((void**)&skey, g_skey);
    cudaGetSymbolAddress((void**)&tkey, g_tkey);
    cudaGetSymbolAddress((void**)&rel, g_rel);
    cudaGetSymbolAddress((void**)&scores, g_scores);
    cudaGetSymbolAddress((void**)&x, g_x);
    cudaGetSymbolAddress((void**)&qin, g_qin);
    cudaGetSymbolAddress((void**)&srcc, g_srcc);
    cudaGetSymbolAddress((void**)&trgc, g_trgc);
    cudaGetSymbolAddress((void**)&wq, g_wq);
    cudaGetSymbolAddress((void**)&ws, g_ws);
    cudaGetSymbolAddress((void**)&wt, g_wt);
    cudaGetSymbolAddress((void**)&wo, g_wo);

    const float inv_sqrt_h = 1.0f / sqrtf((float)HD);
    dim3 blk(256);

    const int smemNT = 2 * (A_STG + BNT_STG) * 4;
    const int smemNN = 2 * (A_STG + BNN_STG) * 4;
    cudaFuncSetAttribute(mma_gemm<true>,
                         cudaFuncAttributeMaxDynamicSharedMemorySize, smemNT);
    cudaFuncSetAttribute(mma_gemm<false>,
                         cudaFuncAttributeMaxDynamicSharedMemorySize, smemNN);

    // 0. tf32 pre-round inputs + weights
    auto cvt = [&](const float* in, float* outp, size_t n) {
        cvt_tf32_kernel<<<(unsigned)(n / 4 / 256), blk>>>(in, outp);
    };
    cvt(query, qin, (size_t)BB * LL * QD);
    cvt(src,   srcc, (size_t)BB * SS * FD);
    cvt(trg,   trgc, (size_t)BB * TT * FD);
    cvt(Wq,    wq,   (size_t)QD * HD);
    cvt(Ws,    ws,   (size_t)FD * HD);
    cvt(Wt,    wt,   (size_t)FD * HD);
    cvt(Wo,    wo,   (size_t)XD * OD);

    // 1. q = query @ Wq + b_q   (output tf32-rounded: feeds GEMM 5)
    mma_gemm<false><<<dim3(HD / 128, (BB * LL) / 128, 1), blk, smemNN>>>(
        qin, QD, 0, wq, HD, 0, b_q, q, HD, 0, QD, 1.f, 0, 1);

    // 2. s_key = src @ Ws + b_s
    mma_gemm<false><<<dim3(HD / 128, (BB * SS) / 128, 1), blk, smemNN>>>(
        srcc, FD, 0, ws, HD, 0, b_s, skey, HD, 0, FD, 1.f, 0, 0);

    // 3. t_key = trg @ Wt + b_t
    mma_gemm<false><<<dim3(HD / 128, (BB * TT) / 128, 1), blk, smemNN>>>(
        trgc, FD, 0, wt, HD, 0, b_t, tkey, HD, 0, FD, 1.f, 0, 0);

    // 4. rel_key = tf32(tanh(s_key + t_key))
    {
        size_t n4 = (size_t)BB * TSD * HD / 4;
        relkey_kernel<<<(unsigned)(n4 / 256), blk>>>(skey, tkey, rel);
    }

    // 5. scores = q . rel^T / sqrt(H)
    mma_gemm<true><<<dim3(TSD / 128, LL / 128, BB), blk, smemNT>>>(
        q, HD, (size_t)LL * HD,
        rel, HD, (size_t)TSD * HD,
        nullptr,
        scores, TSD, (size_t)LL * TSD,
        HD, inv_sqrt_h, 0, 0);

    // 6. softmax (output tf32-rounded)
    softmax_kernel<<<BB * LL, blk>>>(scores);

    // 7. x[:, :768] = tf32(query)
    {
        size_t n4 = (size_t)BB * LL * QD / 4;
        concat_kernel<<<(unsigned)(n4 / 256), blk>>>(query, x);
    }

    // 8. x[:, 768:] = scores @ rel   (output tf32-rounded: feeds GEMM 9)
    mma_gemm<false><<<dim3(HD / 128, LL / 128, BB), blk, smemNN>>>(
        scores, TSD, (size_t)LL * TSD,
        rel, HD, (size_t)TSD * HD,
        nullptr,
        x + QD, XD, (size_t)LL * XD,
        TSD, 1.f, 0, 1);

    // 9. out = relu(x @ Wo + b_o)
    mma_gemm<false><<<dim3(OD / 128, (BB * LL) / 128, 1), blk, smemNN>>>(
        x, XD, 0, wo, OD, 0, b_o, out, OD, 0, XD, 1.f, 1, 0);
}

// round 7
// speedup vs baseline: 1.9527x; 1.2134x over previous
#include <cuda_runtime.h>
#include <cuda_fp16.h>
#include <math.h>
#include <stdint.h>

// Problem dims
constexpr int BB = 32;
constexpr int LL = 256;
constexpr int SS = 64;
constexpr int TT = 64;
constexpr int QD = 768;
constexpr int FD = 1024;
constexpr int HD = 768;
constexpr int OD = 768;
constexpr int TSD = TT * SS;
constexpr int XD = QD + HD;

// Scratch (static device globals)
__device__ __align__(16) __half g_qin_h[(size_t)BB * LL * QD];
__device__ __align__(16) __half g_src_h[(size_t)BB * SS * FD];
__device__ __align__(16) __half g_trg_h[(size_t)BB * TT * FD];
__device__ __align__(16) __half g_wqT[(size_t)HD * QD];   // [n][k]
__device__ __align__(16) __half g_wsT[(size_t)HD * FD];
__device__ __align__(16) __half g_wtT[(size_t)HD * FD];
__device__ __align__(16) __half g_woT[(size_t)OD * XD];
__device__ __align__(16) __half g_qh[(size_t)BB * LL * HD];
__device__ __align__(16) float  g_skey[(size_t)BB * SS * HD];
__device__ __align__(16) float  g_tkey[(size_t)BB * TT * HD];
__device__ __align__(16) __half g_relh[(size_t)BB * TSD * HD];   // [b][ts][h]
__device__ __align__(16) __half g_relTh[(size_t)BB * HD * TSD];  // [b][h][ts]
__device__ __align__(16) float  g_scores[(size_t)BB * LL * TSD];
__device__ __align__(16) __half g_scoresh[(size_t)BB * LL * TSD];
__device__ __align__(16) __half g_xh[(size_t)BB * LL * XD];

__device__ __forceinline__ void cp16(uint32_t dst_smem, const void* src) {
    asm volatile("cp.async.cg.shared.global [%0], [%1], 16;\n"
                 :: "r"(dst_smem), "l"(src));
}
__device__ __forceinline__ void cp_commit() {
    asm volatile("cp.async.commit_group;\n");
}
template <int N>
__device__ __forceinline__ void cp_wait() {
    asm volatile("cp.async.wait_group %0;\n" :: "n"(N));
}

__device__ __forceinline__ void ldsm4(uint32_t* r, uint32_t addr) {
    asm volatile("ldmatrix.sync.aligned.m8n8.x4.shared.b16 {%0,%1,%2,%3}, [%4];"
                 : "=r"(r[0]), "=r"(r[1]), "=r"(r[2]), "=r"(r[3]) : "r"(addr));
}

__device__ __forceinline__ void mma16(float* c, const uint32_t* a,
                                      uint32_t b0, uint32_t b1) {
    asm volatile(
        "mma.sync.aligned.m16n8k16.row.col.f32.f16.f16.f32 "
        "{%0,%1,%2,%3}, {%4,%5,%6,%7}, {%8,%9}, {%0,%1,%2,%3};"
        : "+f"(c[0]), "+f"(c[1]), "+f"(c[2]), "+f"(c[3])
        : "r"(a[0]), "r"(a[1]), "r"(a[2]), "r"(a[3]), "r"(b0), "r"(b1));
}

// ===========================================================================
// FP16 tensor-core NT GEMM: C[m,n] = act(scale * sum_k A[m,k]*B[n,k] + bias)
// A: MxK half row-major (k-major). B: NxK half row-major (k-major).
// Block 128x128, BK=32, 256 threads (8 warps 2m x 4n), warp 64x32.
// Smem: half tiles stride 40 halves (80 B): ldmatrix phases conflict-free
// (banks (20*r) mod 32 distinct). cp.async 2-stage double buffer (R4-proven).
// ===========================================================================
constexpr int HSTR = 40;              // halves per smem row
constexpr int HSTG = 128 * HSTR;      // halves per tile stage

__global__ __launch_bounds__(256) void hgemm_nt(
    const __half* __restrict__ A, int lda, size_t sA_,
    const __half* __restrict__ B, int ldb, size_t sB_,
    const float* __restrict__ bias,
    void* __restrict__ Cv, int ldc, size_t sC_,
    int K, float scale, int do_relu, int out_half)
{
    __shared__ __half sA[2][HSTG];
    __shared__ __half sB[2][HSTG];

    const __half* Ab = A + blockIdx.z * sA_;
    const __half* Bb = B + blockIdx.z * sB_;

    const int tid  = threadIdx.x;
    const int lane = tid & 31;
    const int wid  = tid >> 5;
    const int wm   = wid & 1;
    const int wn   = wid >> 1;
    const int bm   = blockIdx.y * 128;
    const int bn   = blockIdx.x * 128;

    const uint32_t aU = (uint32_t)__cvta_generic_to_shared(&sA[0][0]);
    const uint32_t bU = (uint32_t)__cvta_generic_to_shared(&sB[0][0]);

    // loaders: 512 16B-chunks per tile (128 rows x 4), 2 per thread per tile
    const int lr = tid >> 1;            // 0..127
    const int lc = (tid & 1) * 16;      // 0 or 16 (halves)

    auto issue = [&](int p, int k0) {
        uint32_t ap = aU + (uint32_t)(p * HSTG * 2);
        uint32_t bp = bU + (uint32_t)(p * HSTG * 2);
#pragma unroll
        for (int i = 0; i < 2; i++) {
            int c = lc + 8 * i;
            cp16(ap + (lr * HSTR + c) * 2, Ab + (size_t)(bm + lr) * lda + k0 + c);
            cp16(bp + (lr * HSTR + c) * 2, Bb + (size_t)(bn + lr) * ldb + k0 + c);
        }
    };

    float acc[4][4][4] = {};

    auto compute = [&](int p) {
        uint32_t aBase = aU + (uint32_t)(p * HSTG * 2);
        uint32_t bBase = bU + (uint32_t)(p * HSTG * 2);
        const int lrow = lane & 15;
        const int lkof = (lane >> 4) << 3;
#pragma unroll
        for (int ks = 0; ks < 2; ks++) {
            const int k0s = ks * 16;
            uint32_t a[4][4];
#pragma unroll
            for (int mt = 0; mt < 4; mt++) {
                int m0 = wm * 64 + mt * 16;
                ldsm4(a[mt], aBase + ((m0 + lrow) * HSTR + k0s + lkof) * 2);
            }
            uint32_t bf[2][4];
#pragma unroll
            for (int np = 0; np < 2; np++) {
                int n0 = wn * 32 + np * 16;
                ldsm4(bf[np], bBase + ((n0 + lrow) * HSTR + k0s + lkof) * 2);
            }
#pragma unroll
            for (int nt = 0; nt < 4; nt++) {
                uint32_t b0 = bf[nt >> 1][nt & 1];
                uint32_t b1 = bf[nt >> 1][(nt & 1) + 2];
#pragma unroll
                for (int mt = 0; mt < 4; mt++)
                    mma16(acc[mt][nt], a[mt], b0, b1);
            }
        }
    };

    const int NI = K / 32;
    issue(0, 0);
    cp_commit();

    for (int it = 0; it < NI; it++) {
        if (it + 1 < NI) {
            issue((it + 1) & 1, (it + 1) * 32);
            cp_commit();
            cp_wait<1>();
        } else {
            cp_wait<0>();
        }
        __syncthreads();
        compute(it & 1);
        __syncthreads();
    }

    // Epilogue
#pragma unroll
    for (int nt = 0; nt < 4; nt++) {
        int col = bn + wn * 32 + nt * 8 + (lane & 3) * 2;
        float bv0 = 0.f, bv1 = 0.f;
        if (bias) { bv0 = bias[col]; bv1 = bias[col + 1]; }
#pragma unroll
        for (int mt = 0; mt < 4; mt++) {
            int r0 = bm + wm * 64 + mt * 16 + (lane >> 2);
            float v0 = acc[mt][nt][0] * scale + bv0;
            float v1 = acc[mt][nt][1] * scale + bv1;
            float v2 = acc[mt][nt][2] * scale + bv0;
            float v3 = acc[mt][nt][3] * scale + bv1;
            if (do_relu) {
                v0 = fmaxf(v0, 0.f); v1 = fmaxf(v1, 0.f);
                v2 = fmaxf(v2, 0.f); v3 = fmaxf(v3, 0.f);
            }
            if (out_half) {
                __half* Cb = (__half*)Cv + blockIdx.z * sC_;
                __half2 h0 = __floats2half2_rn(v0, v1);
                __half2 h1 = __floats2half2_rn(v2, v3);
                *(__half2*)(Cb + (size_t)r0 * ldc + col) = h0;
                *(__half2*)(Cb + (size_t)(r0 + 8) * ldc + col) = h1;
            } else {
                float* Cb = (float*)Cv + blockIdx.z * sC_;
                *(float2*)(Cb + (size_t)r0 * ldc + col) = make_float2(v0, v1);
                *(float2*)(Cb + (size_t)(r0 + 8) * ldc + col) = make_float2(v2, v3);
            }
        }
    }
}

// ---------------------------------------------------------------------------
// Prep: fp32 -> half elementwise
__global__ __launch_bounds__(256) void cvt_h_kernel(
    const float* __restrict__ x, __half* __restrict__ y)
{
    size_t i = (size_t)blockIdx.x * blockDim.x + threadIdx.x;
    float4 v = ((const float4*)x)[i];
    __half2 a = __floats2half2_rn(v.x, v.y);
    __half2 b = __floats2half2_rn(v.z, v.w);
    uint2 u;
    u.x = *(uint32_t*)&a; u.y = *(uint32_t*)&b;
    ((uint2*)y)[i] = u;
}

// Prep: transpose + convert: WT[n][k] = half(W[k][n]); grid (Nd/32, Kd/32)
__global__ __launch_bounds__(256) void transpose_h_kernel(
    const float* __restrict__ W, __half* __restrict__ WT, int Kd, int Nd)
{
    __shared__ float t[32][33];
    const int tx = threadIdx.x & 31, ty = threadIdx.x >> 5;
    const int n0 = blockIdx.x * 32, k0 = blockIdx.y * 32;
#pragma unroll
    for (int i = 0; i < 4; i++)
        t[ty + 8 * i][tx] = W[(size_t)(k0 + ty + 8 * i) * Nd + n0 + tx];
    __syncthreads();
#pragma unroll
    for (int i = 0; i < 4; i++)
        WT[(size_t)(n0 + ty + 8 * i) * Kd + k0 + tx] = __float2half(t[tx][ty + 8 * i]);
}

// rel_key = half(tanh(skey[s,:]+tkey[t,:])) in BOTH layouts.
// grid (HD/64, TT, BB), block 256.
__global__ __launch_bounds__(256) void relkey2_kernel(
    const float* __restrict__ skey, const float* __restrict__ tkey,
    __half* __restrict__ rel, __half* __restrict__ relT)
{
    __shared__ float sk[64][65];
    __shared__ float tk[64];
    const int b = blockIdx.z, t = blockIdx.y, h0 = blockIdx.x * 64;
    const int tid = threadIdx.x;
    const int rr  = tid >> 4;
    const int c4  = (tid & 15) * 4;

#pragma unroll
    for (int i = 0; i < 4; i++) {
        int s = rr + 16 * i;
        float4 v = *(const float4*)(skey + ((size_t)b * SS + s) * HD + h0 + c4);
        sk[s][c4 + 0] = v.x; sk[s][c4 + 1] = v.y;
        sk[s][c4 + 2] = v.z; sk[s][c4 + 3] = v.w;
    }
    if (tid < 16) {
        float4 v = *(const float4*)(tkey + ((size_t)b * TT + t) * HD + h0 + tid * 4);
        tk[tid * 4 + 0] = v.x; tk[tid * 4 + 1] = v.y;
        tk[tid * 4 + 2] = v.z; tk[tid * 4 + 3] = v.w;
    }
    __syncthreads();

#pragma unroll
    for (int i = 0; i < 4; i++) {
        int s = rr + 16 * i;
        __half2 h0v = __floats2half2_rn(tanhf(sk[s][c4 + 0] + tk[c4 + 0]),
                                        tanhf(sk[s][c4 + 1] + tk[c4 + 1]));
        __half2 h1v = __floats2half2_rn(tanhf(sk[s][c4 + 2] + tk[c4 + 2]),
                                        tanhf(sk[s][c4 + 3] + tk[c4 + 3]));
        uint2 u; u.x = *(uint32_t*)&h0v; u.y = *(uint32_t*)&h1v;
        *(uint2*)(rel + ((size_t)b * TSD + t * 64 + s) * HD + h0 + c4) = u;
    }
#pragma unroll
    for (int i = 0; i < 4; i++) {
        int h = rr + 16 * i;
        float thv = tk[h];
        __half2 h0v = __floats2half2_rn(tanhf(sk[c4 + 0][h] + thv),
                                        tanhf(sk[c4 + 1][h] + thv));
        __half2 h1v = __floats2half2_rn(tanhf(sk[c4 + 2][h] + thv),
                                        tanhf(sk[c4 + 3][h] + thv));
        uint2 u; u.x = *(uint32_t*)&h0v; u.y = *(uint32_t*)&h1v;
        *(uint2*)(relT + ((size_t)b * HD + h0 + h) * TSD + t * 64 + c4) = u;
    }
}

// Softmax over 4096 per row: fp32 in, half out.
__global__ __launch_bounds__(256) void softmax_kernel(
    const float* __restrict__ data, __half* __restrict__ outh)
{
    const float* row = data + (size_t)blockIdx.x * TSD;
    __half* rowh = outh + (size_t)blockIdx.x * TSD;
    const int tid = threadIdx.x;
    float v[16];
    float m = -INFINITY;
#pragma unroll
    for (int i = 0; i < 16; i++) {
        v[i] = row[tid + i * 256];
        m = fmaxf(m, v[i]);
    }
#pragma unroll
    for (int o = 16; o; o >>= 1) m = fmaxf(m, __shfl_xor_sync(0xffffffffu, m, o));
    __shared__ float redm[8];
    __shared__ float reds[8];
    if ((tid & 31) == 0) redm[tid >> 5] = m;
    __syncthreads();
#pragma unroll
    for (int w = 0; w < 8; w++) m = fmaxf(m, redm[w]);
    float s = 0.f;
#pragma unroll
    for (int i = 0; i < 16; i++) {
        v[i] = expf(v[i] - m);
        s += v[i];
    }
#pragma unroll
    for (int o = 16; o; o >>= 1) s += __shfl_xor_sync(0xffffffffu, s, o);
    if ((tid & 31) == 0) reds[tid >> 5] = s;
    __syncthreads();
    s = 0.f;
#pragma unroll
    for (int w = 0; w < 8; w++) s += reds[w];
    float inv = 1.f / s;
#pragma unroll
    for (int i = 0; i < 16; i++)
        rowh[tid + i * 256] = __float2half(v[i] * inv);
}

// x_h[:, :768] = half(query)
__global__ __launch_bounds__(256) void concat_kernel(
    const float* __restrict__ q, __half* __restrict__ x)
{
    const size_t Q4 = QD / 4;
    size_t idx = (size_t)blockIdx.x * blockDim.x + threadIdx.x;
    size_t rowi = idx / Q4;
    size_t c4 = idx % Q4;
    float4 v = ((const float4*)q)[idx];
    __half2 a = __floats2half2_rn(v.x, v.y);
    __half2 b = __floats2half2_rn(v.z, v.w);
    uint2 u; u.x = *(uint32_t*)&a; u.y = *(uint32_t*)&b;
    *(uint2*)(x + rowi * XD + c4 * 4) = u;
}

// ---------------------------------------------------------------------------
extern "C" void kernel_launch(void* const* d_in, const int* in_sizes, int n_in,
                              void* d_out, int out_size)
{
    const float* query = (const float*)d_in[0];
    const float* src   = (const float*)d_in[1];
    const float* trg   = (const float*)d_in[2];
    const float* Wq    = (const float*)d_in[3];
    const float* b_q   = (const float*)d_in[4];
    const float* Ws    = (const float*)d_in[5];
    const float* b_s   = (const float*)d_in[6];
    const float* Wt    = (const float*)d_in[7];
    const float* b_t   = (const float*)d_in[8];
    const float* Wo    = (const float*)d_in[9];
    const float* b_o   = (const float*)d_in[10];
    float* out = (float*)d_out;

    __half *qin_h, *src_h, *trg_h, *wqT, *wsT, *wtT, *woT;
    __half *qh, *relh, *relTh, *scoresh, *xh;
    float *skey, *tkey, *scores;
    cudaGetSymbolAddress((void**)&qin_h, g_qin_h);
    cudaGetSymbolAddress((void**)&src_h, g_src_h);
    cudaGetSymbolAddress((void**)&trg_h, g_trg_h);
    cudaGetSymbolAddress((void**)&wqT, g_wqT);
    cudaGetSymbolAddress((void**)&wsT, g_wsT);
    cudaGetSymbolAddress((void**)&wtT, g_wtT);
    cudaGetSymbolAddress((void**)&woT, g_woT);
    cudaGetSymbolAddress((void**)&qh, g_qh);
    cudaGetSymbolAddress((void**)&skey, g_skey);
    cudaGetSymbolAddress((void**)&tkey, g_tkey);
    cudaGetSymbolAddress((void**)&relh, g_relh);
    cudaGetSymbolAddress((void**)&relTh, g_relTh);
    cudaGetSymbolAddress((void**)&scores, g_scores);
    cudaGetSymbolAddress((void**)&scoresh, g_scoresh);
    cudaGetSymbolAddress((void**)&xh, g_xh);

    const float inv_sqrt_h = 1.0f / sqrtf((float)HD);
    dim3 blk(256);

    // 0. prep: inputs -> half, weights -> transposed half [n][k]
    auto cvt = [&](const float* in, __half* outp, size_t n) {
        cvt_h_kernel<<<(unsigned)(n / 4 / 256), blk>>>(in, outp);
    };
    cvt(query, qin_h, (size_t)BB * LL * QD);
    cvt(src,   src_h, (size_t)BB * SS * FD);
    cvt(trg,   trg_h, (size_t)BB * TT * FD);
    transpose_h_kernel<<<dim3(HD / 32, QD / 32), blk>>>(Wq, wqT, QD, HD);
    transpose_h_kernel<<<dim3(HD / 32, FD / 32), blk>>>(Ws, wsT, FD, HD);
    transpose_h_kernel<<<dim3(HD / 32, FD / 32), blk>>>(Wt, wtT, FD, HD);
    transpose_h_kernel<<<dim3(OD / 32, XD / 32), blk>>>(Wo, woT, XD, OD);

    // 1. q = query @ Wq + b_q  -> half (feeds GEMM 5)
    hgemm_nt<<<dim3(HD / 128, (BB * LL) / 128, 1), blk>>>(
        qin_h, QD, 0, wqT, QD, 0, b_q, qh, HD, 0, QD, 1.f, 0, 1);

    // 2. s_key = src @ Ws + b_s  -> fp32 (feeds tanh)
    hgemm_nt<<<dim3(HD / 128, (BB * SS) / 128, 1), blk>>>(
        src_h, FD, 0, wsT, FD, 0, b_s, skey, HD, 0, FD, 1.f, 0, 0);

    // 3. t_key = trg @ Wt + b_t  -> fp32
    hgemm_nt<<<dim3(HD / 128, (BB * TT) / 128, 1), blk>>>(
        trg_h, FD, 0, wtT, FD, 0, b_t, tkey, HD, 0, FD, 1.f, 0, 0);

    // 4. rel (+ relT) = half(tanh(skey + tkey))
    relkey2_kernel<<<dim3(HD / 64, TT, BB), blk>>>(skey, tkey, relh, relTh);

    // 5. scores = q . rel^T / sqrt(H)  -> fp32
    hgemm_nt<<<dim3(TSD / 128, LL / 128, BB), blk>>>(
        qh, HD, (size_t)LL * HD,
        relh, HD, (size_t)TSD * HD,
        nullptr,
        scores, TSD, (size_t)LL * TSD,
        HD, inv_sqrt_h, 0, 0);

    // 6. softmax -> half
    softmax_kernel<<<BB * LL, blk>>>(scores, scoresh);

    // 7. x_h[:, :768] = half(query)
    {
        size_t n4 = (size_t)BB * LL * QD / 4;
        concat_kernel<<<(unsigned)(n4 / 256), blk>>>(query, xh);
    }

    // 8. x_h[:, 768:] = scores . relT^T  (= scores @ rel) -> half
    hgemm_nt<<<dim3(HD / 128, LL / 128, BB), blk>>>(
        scoresh, TSD, (size_t)LL * TSD,
        relTh, TSD, (size_t)HD * TSD,
        nullptr,
        xh + QD, XD, (size_t)LL * XD,
        TSD, 1.f, 0, 1);

    // 9. out = relu(x @ Wo + b_o) -> fp32
    hgemm_nt<<<dim3(OD / 128, (BB * LL) / 128, 1), blk>>>(
        xh, XD, 0, woT, XD, 0, b_o, out, OD, 0, XD, 1.f, 1, 0);
}

// round 8
// speedup vs baseline: 2.1784x; 1.1156x over previous
#include <cuda_runtime.h>
#include <cuda_fp16.h>
#include <math.h>
#include <stdint.h>

// Problem dims
constexpr int BB = 32;
constexpr int LL = 256;
constexpr int SS = 64;
constexpr int TT = 64;
constexpr int QD = 768;
constexpr int FD = 1024;
constexpr int HD = 768;
constexpr int OD = 768;
constexpr int TSD = TT * SS;
constexpr int XD = QD + HD;

// Scratch (static device globals)
__device__ __align__(16) __half g_qin_h[(size_t)BB * LL * QD];
__device__ __align__(16) __half g_src_h[(size_t)BB * SS * FD];
__device__ __align__(16) __half g_trg_h[(size_t)BB * TT * FD];
__device__ __align__(16) __half g_wqT[(size_t)HD * QD];   // [n][k]
__device__ __align__(16) __half g_wsT[(size_t)HD * FD];
__device__ __align__(16) __half g_wtT[(size_t)HD * FD];
__device__ __align__(16) __half g_woT[(size_t)OD * XD];
__device__ __align__(16) __half g_qh[(size_t)BB * LL * HD];
__device__ __align__(16) float  g_skey[(size_t)BB * SS * HD];
__device__ __align__(16) float  g_tkey[(size_t)BB * TT * HD];
__device__ __align__(16) __half g_relh[(size_t)BB * TSD * HD];   // [b][ts][h]
__device__ __align__(16) float  g_scores[(size_t)BB * LL * TSD];
__device__ __align__(16) __half g_scoresh[(size_t)BB * LL * TSD];
__device__ __align__(16) __half g_xh[(size_t)BB * LL * XD];

__device__ __forceinline__ void cp16(uint32_t dst_smem, const void* src) {
    asm volatile("cp.async.cg.shared.global [%0], [%1], 16;\n"
                 :: "r"(dst_smem), "l"(src));
}
__device__ __forceinline__ void cp_commit() {
    asm volatile("cp.async.commit_group;\n");
}
template <int N>
__device__ __forceinline__ void cp_wait() {
    asm volatile("cp.async.wait_group %0;\n" :: "n"(N));
}

__device__ __forceinline__ void ldsm4(uint32_t* r, uint32_t addr) {
    asm volatile("ldmatrix.sync.aligned.m8n8.x4.shared.b16 {%0,%1,%2,%3}, [%4];"
                 : "=r"(r[0]), "=r"(r[1]), "=r"(r[2]), "=r"(r[3]) : "r"(addr));
}
__device__ __forceinline__ void ldsm4t(uint32_t* r, uint32_t addr) {
    asm volatile("ldmatrix.sync.aligned.m8n8.x4.trans.shared.b16 {%0,%1,%2,%3}, [%4];"
                 : "=r"(r[0]), "=r"(r[1]), "=r"(r[2]), "=r"(r[3]) : "r"(addr));
}

__device__ __forceinline__ void mma16(float* c, const uint32_t* a,
                                      uint32_t b0, uint32_t b1) {
    asm volatile(
        "mma.sync.aligned.m16n8k16.row.col.f32.f16.f16.f32 "
        "{%0,%1,%2,%3}, {%4,%5,%6,%7}, {%8,%9}, {%0,%1,%2,%3};"
        : "+f"(c[0]), "+f"(c[1]), "+f"(c[2]), "+f"(c[3])
        : "r"(a[0]), "r"(a[1]), "r"(a[2]), "r"(a[3]), "r"(b0), "r"(b1));
}

// ===========================================================================
// FP16 tensor-core GEMM, 3-stage cp.async ring, one __syncthreads per iter.
//   NT=true : C = act(scale * A(MxK) @ B(NxK)^T + bias)   (B k-major)
//   NT=false: C = act(scale * A(MxK) @ B(KxN)  + bias)    (B n-major, NN)
// Block 128x128, BK=32, 256 threads (8 warps 2m x 4n), warp 64x32.
// A / NT-B smem: [row][k] stride 40 halves (ldmatrix phases conflict-free).
// NN-B smem: [k=32][n=128] stride 136 halves; ldmatrix.trans rows at 272B
//   spacing hit banks {4r..4r+3} mod 32, all distinct -> conflict-free.
//   x4.trans mats: mat0=(k0-7,n0-7) mat1=(k8-15,n0-7) mat2=(k0-7,n8-15)
//   mat3=(k8-15,n8-15); n-block j uses b0=reg[2j], b1=reg[2j+1].
// ===========================================================================
constexpr int NST  = 3;
constexpr int HSTR = 40;              // halves per A/NT-B smem row
constexpr int HSTG = 128 * HSTR;      // halves per A/NT-B stage
constexpr int BNNSTR = 136;
constexpr int BNNSTG = 32 * BNNSTR;   // halves per NN-B stage
constexpr int SMEM_BYTES = (NST * HSTG + NST * HSTG) * 2;  // 61440 (max case)

template <bool NT>
__global__ __launch_bounds__(256) void hgemm(
    const __half* __restrict__ A, int lda, size_t sA_,
    const __half* __restrict__ B, int ldb, size_t sB_,
    const float* __restrict__ bias,
    void* __restrict__ Cv, int ldc, size_t sC_,
    int K, float scale, int do_relu, int out_half)
{
    extern __shared__ __half smh[];
    __half* sA = smh;
    __half* sB = smh + NST * HSTG;
    constexpr int BSTG = NT ? HSTG : BNNSTG;

    const __half* Ab = A + blockIdx.z * sA_;
    const __half* Bb = B + blockIdx.z * sB_;

    const int tid  = threadIdx.x;
    const int lane = tid & 31;
    const int wid  = tid >> 5;
    const int wm   = wid & 1;
    const int wn   = wid >> 1;
    const int bm   = blockIdx.y * 128;
    const int bn   = blockIdx.x * 128;

    const uint32_t aU = (uint32_t)__cvta_generic_to_shared(sA);
    const uint32_t bU = (uint32_t)__cvta_generic_to_shared(sB);

    // A loader: 128 rows x 32 halves = 512 chunks, 2/thread
    const int lr = tid >> 1;
    const int lc = (tid & 1) * 16;
    // NN B loader: 32 rows x 128 halves = 512 chunks, 2/thread
    const int nbr = tid >> 4;           // 0..15 (+16)
    const int nbc = (tid & 15) * 8;     // halves

    auto issue = [&](int st, int k0) {
        uint32_t ap = aU + (uint32_t)(st * HSTG * 2);
#pragma unroll
        for (int i = 0; i < 2; i++) {
            int c = lc + 8 * i;
            cp16(ap + (lr * HSTR + c) * 2, Ab + (size_t)(bm + lr) * lda + k0 + c);
        }
        uint32_t bp = bU + (uint32_t)(st * BSTG * 2);
        if (NT) {
#pragma unroll
            for (int i = 0; i < 2; i++) {
                int c = lc + 8 * i;
                cp16(bp + (lr * HSTR + c) * 2, Bb + (size_t)(bn + lr) * ldb + k0 + c);
            }
        } else {
#pragma unroll
            for (int i = 0; i < 2; i++) {
                int r = nbr + 16 * i;
                cp16(bp + (r * BNNSTR + nbc) * 2,
                     Bb + (size_t)(k0 + r) * ldb + bn + nbc);
            }
        }
    };

    float acc[4][4][4] = {};

    auto compute = [&](int st) {
        uint32_t aBase = aU + (uint32_t)(st * HSTG * 2);
        uint32_t bBase = bU + (uint32_t)(st * BSTG * 2);
        const int lrow = lane & 15;
        const int lhalf = lane >> 4;           // 0/1
#pragma unroll
        for (int ks = 0; ks < 2; ks++) {
            const int k0s = ks * 16;
            uint32_t a[4][4];
#pragma unroll
            for (int mt = 0; mt < 4; mt++) {
                int m0 = wm * 64 + mt * 16;
                ldsm4(a[mt], aBase + ((m0 + lrow) * HSTR + k0s + lhalf * 8) * 2);
            }
            uint32_t bf[2][4];
#pragma unroll
            for (int np = 0; np < 2; np++) {
                int n0 = wn * 32 + np * 16;
                if (NT) {
                    ldsm4(bf[np], bBase + ((n0 + lrow) * HSTR + k0s + lhalf * 8) * 2);
                } else {
                    ldsm4t(bf[np], bBase + ((k0s + lrow) * BNNSTR + n0 + lhalf * 8) * 2);
                }
            }
#pragma unroll
            for (int nt = 0; nt < 4; nt++) {
                uint32_t b0, b1;
                if (NT) {
                    b0 = bf[nt >> 1][nt & 1];
                    b1 = bf[nt >> 1][(nt & 1) + 2];
                } else {
                    b0 = bf[nt >> 1][(nt & 1) * 2];
                    b1 = bf[nt >> 1][(nt & 1) * 2 + 1];
                }
#pragma unroll
                for (int mt = 0; mt < 4; mt++)
                    mma16(acc[mt][nt], a[mt], b0, b1);
            }
        }
    };

    const int NI = K / 32;
    issue(0, 0); cp_commit();
    if (NI > 1) { issue(1, 32); cp_commit(); }

    for (int it = 0; it < NI; it++) {
        if (it + 1 < NI) cp_wait<1>(); else cp_wait<0>();
        __syncthreads();
        if (it + 2 < NI) {
            issue((it + 2) % NST, (it + 2) * 32);
            cp_commit();
        }
        compute(it % NST);
    }

    // Epilogue
#pragma unroll
    for (int nt = 0; nt < 4; nt++) {
        int col = bn + wn * 32 + nt * 8 + (lane & 3) * 2;
        float bv0 = 0.f, bv1 = 0.f;
        if (bias) { bv0 = bias[col]; bv1 = bias[col + 1]; }
#pragma unroll
        for (int mt = 0; mt < 4; mt++) {
            int r0 = bm + wm * 64 + mt * 16 + (lane >> 2);
            float v0 = acc[mt][nt][0] * scale + bv0;
            float v1 = acc[mt][nt][1] * scale + bv1;
            float v2 = acc[mt][nt][2] * scale + bv0;
            float v3 = acc[mt][nt][3] * scale + bv1;
            if (do_relu) {
                v0 = fmaxf(v0, 0.f); v1 = fmaxf(v1, 0.f);
                v2 = fmaxf(v2, 0.f); v3 = fmaxf(v3, 0.f);
            }
            if (out_half) {
                __half* Cb = (__half*)Cv + blockIdx.z * sC_;
                __half2 h0 = __floats2half2_rn(v0, v1);
                __half2 h1 = __floats2half2_rn(v2, v3);
                *(__half2*)(Cb + (size_t)r0 * ldc + col) = h0;
                *(__half2*)(Cb + (size_t)(r0 + 8) * ldc + col) = h1;
            } else {
                float* Cb = (float*)Cv + blockIdx.z * sC_;
                *(float2*)(Cb + (size_t)r0 * ldc + col) = make_float2(v0, v1);
                *(float2*)(Cb + (size_t)(r0 + 8) * ldc + col) = make_float2(v2, v3);
            }
        }
    }
}

// ---------------------------------------------------------------------------
// Prep: fp32 -> half elementwise
__global__ __launch_bounds__(256) void cvt_h_kernel(
    const float* __restrict__ x, __half* __restrict__ y)
{
    size_t i = (size_t)blockIdx.x * blockDim.x + threadIdx.x;
    float4 v = ((const float4*)x)[i];
    __half2 a = __floats2half2_rn(v.x, v.y);
    __half2 b = __floats2half2_rn(v.z, v.w);
    uint2 u;
    u.x = *(uint32_t*)&a; u.y = *(uint32_t*)&b;
    ((uint2*)y)[i] = u;
}

// Prep: transpose + convert: WT[n][k] = half(W[k][n])
__global__ __launch_bounds__(256) void transpose_h_kernel(
    const float* __restrict__ W, __half* __restrict__ WT, int Kd, int Nd)
{
    __shared__ float t[32][33];
    const int tx = threadIdx.x & 31, ty = threadIdx.x >> 5;
    const int n0 = blockIdx.x * 32, k0 = blockIdx.y * 32;
#pragma unroll
    for (int i = 0; i < 4; i++)
        t[ty + 8 * i][tx] = W[(size_t)(k0 + ty + 8 * i) * Nd + n0 + tx];
    __syncthreads();
#pragma unroll
    for (int i = 0; i < 4; i++)
        WT[(size_t)(n0 + ty + 8 * i) * Kd + k0 + tx] = __float2half(t[tx][ty + 8 * i]);
}

// rel[b][t*SS+s][h] = half(tanh(skey[b,s,h] + tkey[b,t,h]))
// Streaming; skey/tkey (192 KB per batch) stay resident in L2.
__global__ __launch_bounds__(256) void relkey_kernel(
    const float* __restrict__ skey, const float* __restrict__ tkey,
    __half* __restrict__ rel)
{
    const size_t H4 = HD / 4;
    size_t idx = (size_t)blockIdx.x * blockDim.x + threadIdx.x;
    size_t h4 = idx % H4;
    size_t rest = idx / H4;
    int s = (int)(rest % SS); rest /= SS;
    int t = (int)(rest % TT);
    int b = (int)(rest / TT);
    float4 sv = ((const float4*)skey)[((size_t)b * SS + s) * H4 + h4];
    float4 tv = ((const float4*)tkey)[((size_t)b * TT + t) * H4 + h4];
    __half2 h0 = __floats2half2_rn(tanhf(sv.x + tv.x), tanhf(sv.y + tv.y));
    __half2 h1 = __floats2half2_rn(tanhf(sv.z + tv.z), tanhf(sv.w + tv.w));
    uint2 u; u.x = *(uint32_t*)&h0; u.y = *(uint32_t*)&h1;
    ((uint2*)rel)[idx] = u;
}

// Softmax over 4096 per row: fp32 in, half out.
__global__ __launch_bounds__(256) void softmax_kernel(
    const float* __restrict__ data, __half* __restrict__ outh)
{
    const float* row = data + (size_t)blockIdx.x * TSD;
    __half* rowh = outh + (size_t)blockIdx.x * TSD;
    const int tid = threadIdx.x;
    float v[16];
    float m = -INFINITY;
#pragma unroll
    for (int i = 0; i < 16; i++) {
        v[i] = row[tid + i * 256];
        m = fmaxf(m, v[i]);
    }
#pragma unroll
    for (int o = 16; o; o >>= 1) m = fmaxf(m, __shfl_xor_sync(0xffffffffu, m, o));
    __shared__ float redm[8];
    __shared__ float reds[8];
    if ((tid & 31) == 0) redm[tid >> 5] = m;
    __syncthreads();
#pragma unroll
    for (int w = 0; w < 8; w++) m = fmaxf(m, redm[w]);
    float s = 0.f;
#pragma unroll
    for (int i = 0; i < 16; i++) {
        v[i] = expf(v[i] - m);
        s += v[i];
    }
#pragma unroll
    for (int o = 16; o; o >>= 1) s += __shfl_xor_sync(0xffffffffu, s, o);
    if ((tid & 31) == 0) reds[tid >> 5] = s;
    __syncthreads();
    s = 0.f;
#pragma unroll
    for (int w = 0; w < 8; w++) s += reds[w];
    float inv = 1.f / s;
#pragma unroll
    for (int i = 0; i < 16; i++)
        rowh[tid + i * 256] = __float2half(v[i] * inv);
}

// x_h[:, :768] = half(query)
__global__ __launch_bounds__(256) void concat_kernel(
    const float* __restrict__ q, __half* __restrict__ x)
{
    const size_t Q4 = QD / 4;
    size_t idx = (size_t)blockIdx.x * blockDim.x + threadIdx.x;
    size_t rowi = idx / Q4;
    size_t c4 = idx % Q4;
    float4 v = ((const float4*)q)[idx];
    __half2 a = __floats2half2_rn(v.x, v.y);
    __half2 b = __floats2half2_rn(v.z, v.w);
    uint2 u; u.x = *(uint32_t*)&a; u.y = *(uint32_t*)&b;
    *(uint2*)(x + rowi * XD + c4 * 4) = u;
}

// ---------------------------------------------------------------------------
extern "C" void kernel_launch(void* const* d_in, const int* in_sizes, int n_in,
                              void* d_out, int out_size)
{
    const float* query = (const float*)d_in[0];
    const float* src   = (const float*)d_in[1];
    const float* trg   = (const float*)d_in[2];
    const float* Wq    = (const float*)d_in[3];
    const float* b_q   = (const float*)d_in[4];
    const float* Ws    = (const float*)d_in[5];
    const float* b_s   = (const float*)d_in[6];
    const float* Wt    = (const float*)d_in[7];
    const float* b_t   = (const float*)d_in[8];
    const float* Wo    = (const float*)d_in[9];
    const float* b_o   = (const float*)d_in[10];
    float* out = (float*)d_out;

    __half *qin_h, *src_h, *trg_h, *wqT, *wsT, *wtT, *woT;
    __half *qh, *relh, *scoresh, *xh;
    float *skey, *tkey, *scores;
    cudaGetSymbolAddress((void**)&qin_h, g_qin_h);
    cudaGetSymbolAddress((void**)&src_h, g_src_h);
    cudaGetSymbolAddress((void**)&trg_h, g_trg_h);
    cudaGetSymbolAddress((void**)&wqT, g_wqT);
    cudaGetSymbolAddress((void**)&wsT, g_wsT);
    cudaGetSymbolAddress((void**)&wtT, g_wtT);
    cudaGetSymbolAddress((void**)&woT, g_woT);
    cudaGetSymbolAddress((void**)&qh, g_qh);
    cudaGetSymbolAddress((void**)&skey, g_skey);
    cudaGetSymbolAddress((void**)&tkey, g_tkey);
    cudaGetSymbolAddress((void**)&relh, g_relh);
    cudaGetSymbolAddress((void**)&scores, g_scores);
    cudaGetSymbolAddress((void**)&scoresh, g_scoresh);
    cudaGetSymbolAddress((void**)&xh, g_xh);

    const float inv_sqrt_h = 1.0f / sqrtf((float)HD);
    dim3 blk(256);

    cudaFuncSetAttribute(hgemm<true>,
                         cudaFuncAttributeMaxDynamicSharedMemorySize, SMEM_BYTES);
    cudaFuncSetAttribute(hgemm<false>,
                         cudaFuncAttributeMaxDynamicSharedMemorySize, SMEM_BYTES);

    // 0. prep
    auto cvt = [&](const float* in, __half* outp, size_t n) {
        cvt_h_kernel<<<(unsigned)(n / 4 / 256), blk>>>(in, outp);
    };
    cvt(query, qin_h, (size_t)BB * LL * QD);
    cvt(src,   src_h, (size_t)BB * SS * FD);
    cvt(trg,   trg_h, (size_t)BB * TT * FD);
    transpose_h_kernel<<<dim3(HD / 32, QD / 32), blk>>>(Wq, wqT, QD, HD);
    transpose_h_kernel<<<dim3(HD / 32, FD / 32), blk>>>(Ws, wsT, FD, HD);
    transpose_h_kernel<<<dim3(HD / 32, FD / 32), blk>>>(Wt, wtT, FD, HD);
    transpose_h_kernel<<<dim3(OD / 32, XD / 32), blk>>>(Wo, woT, XD, OD);

    // 1. q = query @ Wq + b_q  -> half
    hgemm<true><<<dim3(HD / 128, (BB * LL) / 128, 1), blk, SMEM_BYTES>>>(
        qin_h, QD, 0, wqT, QD, 0, b_q, qh, HD, 0, QD, 1.f, 0, 1);

    // 2. s_key = src @ Ws + b_s  -> fp32
    hgemm<true><<<dim3(HD / 128, (BB * SS) / 128, 1), blk, SMEM_BYTES>>>(
        src_h, FD, 0, wsT, FD, 0, b_s, skey, HD, 0, FD, 1.f, 0, 0);

    // 3. t_key = trg @ Wt + b_t  -> fp32
    hgemm<true><<<dim3(HD / 128, (BB * TT) / 128, 1), blk, SMEM_BYTES>>>(
        trg_h, FD, 0, wtT, FD, 0, b_t, tkey, HD, 0, FD, 1.f, 0, 0);

    // 4. rel = half(tanh(skey + tkey))
    {
        size_t n4 = (size_t)BB * TSD * HD / 4;
        relkey_kernel<<<(unsigned)(n4 / 256), blk>>>(skey, tkey, relh);
    }

    // 5. scores = q . rel^T / sqrt(H)  -> fp32   [NT]
    hgemm<true><<<dim3(TSD / 128, LL / 128, BB), blk, SMEM_BYTES>>>(
        qh, HD, (size_t)LL * HD,
        relh, HD, (size_t)TSD * HD,
        nullptr,
        scores, TSD, (size_t)LL * TSD,
        HD, inv_sqrt_h, 0, 0);

    // 6. softmax -> half
    softmax_kernel<<<BB * LL, blk>>>(scores, scoresh);

    // 7. x_h[:, :768] = half(query)
    {
        size_t n4 = (size_t)BB * LL * QD / 4;
        concat_kernel<<<(unsigned)(n4 / 256), blk>>>(query, xh);
    }

    // 8. x_h[:, 768:] = scores @ rel  -> half   [NN, rel consumed directly]
    hgemm<false><<<dim3(HD / 128, LL / 128, BB), blk, SMEM_BYTES>>>(
        scoresh, TSD, (size_t)LL * TSD,
        relh, HD, (size_t)TSD * HD,
        nullptr,
        xh + QD, XD, (size_t)LL * XD,
        TSD, 1.f, 0, 1);

    // 9. out = relu(x @ Wo + b_o) -> fp32
    hgemm<true><<<dim3(OD / 128, (BB * LL) / 128, 1), blk, SMEM_BYTES>>>(
        xh, XD, 0, woT, XD, 0, b_o, out, OD, 0, XD, 1.f, 1, 0);
}

// round 11
// speedup vs baseline: 2.7864x; 1.2791x over previous
#include <cuda_runtime.h>
#include <cuda_fp16.h>
#include <math.h>
#include <stdint.h>

// Problem dims
constexpr int BB = 32;
constexpr int LL = 256;
constexpr int SS = 64;
constexpr int TT = 64;
constexpr int QD = 768;
constexpr int FD = 1024;
constexpr int HD = 768;
constexpr int OD = 768;
constexpr int TSD = TT * SS;
constexpr int XD = QD + HD;

// Scratch (static device globals)
__device__ __align__(16) __half g_qin_h[(size_t)BB * LL * QD];
__device__ __align__(16) __half g_src_h[(size_t)BB * SS * FD];
__device__ __align__(16) __half g_trg_h[(size_t)BB * TT * FD];
__device__ __align__(16) __half g_wqT[(size_t)HD * QD];   // [n][k]
__device__ __align__(16) __half g_wsT[(size_t)HD * FD];
__device__ __align__(16) __half g_wtT[(size_t)HD * FD];
__device__ __align__(16) __half g_woT[(size_t)OD * XD];
__device__ __align__(16) __half g_qh[(size_t)BB * LL * HD];
__device__ __align__(16) float  g_skey[(size_t)BB * SS * HD];
__device__ __align__(16) float  g_tkey[(size_t)BB * TT * HD];
__device__ __align__(16) __half g_relh[(size_t)BB * TSD * HD];   // [b][ts][h]
__device__ __align__(16) __half g_scoresh[(size_t)BB * LL * TSD];
__device__ __align__(16) __half g_xh[(size_t)BB * LL * XD];

__device__ __forceinline__ void cp16(uint32_t dst_smem, const void* src) {
    asm volatile("cp.async.cg.shared.global [%0], [%1], 16;\n"
                 :: "r"(dst_smem), "l"(src));
}
__device__ __forceinline__ void cp_commit() {
    asm volatile("cp.async.commit_group;\n");
}
template <int N>
__device__ __forceinline__ void cp_wait() {
    asm volatile("cp.async.wait_group %0;\n" :: "n"(N));
}

__device__ __forceinline__ void ldsm4(uint32_t* r, uint32_t addr) {
    asm volatile("ldmatrix.sync.aligned.m8n8.x4.shared.b16 {%0,%1,%2,%3}, [%4];"
                 : "=r"(r[0]), "=r"(r[1]), "=r"(r[2]), "=r"(r[3]) : "r"(addr));
}
__device__ __forceinline__ void ldsm4t(uint32_t* r, uint32_t addr) {
    asm volatile("ldmatrix.sync.aligned.m8n8.x4.trans.shared.b16 {%0,%1,%2,%3}, [%4];"
                 : "=r"(r[0]), "=r"(r[1]), "=r"(r[2]), "=r"(r[3]) : "r"(addr));
}

__device__ __forceinline__ void mma16(float* c, const uint32_t* a,
                                      uint32_t b0, uint32_t b1) {
    asm volatile(
        "mma.sync.aligned.m16n8k16.row.col.f32.f16.f16.f32 "
        "{%0,%1,%2,%3}, {%4,%5,%6,%7}, {%8,%9}, {%0,%1,%2,%3};"
        : "+f"(c[0]), "+f"(c[1]), "+f"(c[2]), "+f"(c[3])
        : "r"(a[0]), "r"(a[1]), "r"(a[2]), "r"(a[3]), "r"(b0), "r"(b1));
}

// ===========================================================================
// FP16 tensor-core GEMM, BK=64, 3-stage cp.async ring, one sync per iter.
//   NT=true : C = act(scale * A(MxK) @ B(NxK)^T + bias)   (B k-major)
//   NT=false: C = act(scale * A(MxK) @ B(KxN)  + bias)    (B n-major)
// Block 128x128, 256 threads (8 warps 2m x 4n), warp 64x32.
// A / NT-B smem: [row][k] stride 72 halves (144 B): each 8-row ldmatrix
//   phase covers words 4r..4r+3 mod 32 = all 32 banks, conflict-free.
// NN-B smem: [k=64][n=128] stride 136 halves (conflict-free, proven R7).
// ===========================================================================
constexpr int NST  = 3;
constexpr int BK   = 64;
constexpr int HSTR = 72;               // halves per A/NT-B smem row
constexpr int HSTG = 128 * HSTR;       // 9216 halves per stage
constexpr int BNNSTR = 136;
constexpr int BNNSTG = 64 * BNNSTR;    // 8704 halves per stage
constexpr int SMEM_BYTES = NST * (HSTG + HSTG) * 2;   // 110592 B

template <bool NT>
__global__ __launch_bounds__(256) void hgemm(
    const __half* __restrict__ A, int lda, size_t sA_,
    const __half* __restrict__ B, int ldb, size_t sB_,
    const float* __restrict__ bias,
    void* __restrict__ Cv, int ldc, size_t sC_,
    int K, float scale, int do_relu, int out_half)
{
    extern __shared__ __half smh[];
    __half* sA = smh;
    __half* sB = smh + NST * HSTG;
    constexpr int BSTG = NT ? HSTG : BNNSTG;

    const __half* Ab = A + blockIdx.z * sA_;
    const __half* Bb = B + blockIdx.z * sB_;

    const int tid  = threadIdx.x;
    const int lane = tid & 31;
    const int wid  = tid >> 5;
    const int wm   = wid & 1;
    const int wn   = wid >> 1;
    const int bm   = blockIdx.y * 128;
    const int bn   = blockIdx.x * 128;

    const uint32_t aU = (uint32_t)__cvta_generic_to_shared(sA);
    const uint32_t bU = (uint32_t)__cvta_generic_to_shared(sB);

    auto issue = [&](int st, int k0) {
        uint32_t ap = aU + (uint32_t)(st * HSTG * 2);
        // A: 128 rows x 64 halves = 1024 chunks, 4/thread
#pragma unroll
        for (int i = 0; i < 4; i++) {
            int c = tid + 256 * i;
            int r = c >> 3, col = (c & 7) * 8;
            cp16(ap + (r * HSTR + col) * 2, Ab + (size_t)(bm + r) * lda + k0 + col);
        }
        uint32_t bp = bU + (uint32_t)(st * BSTG * 2);
        if (NT) {
#pragma unroll
            for (int i = 0; i < 4; i++) {
                int c = tid + 256 * i;
                int r = c >> 3, col = (c & 7) * 8;
                cp16(bp + (r * HSTR + col) * 2, Bb + (size_t)(bn + r) * ldb + k0 + col);
            }
        } else {
            // B: 64 rows x 128 halves = 1024 chunks, 4/thread
#pragma unroll
            for (int i = 0; i < 4; i++) {
                int c = tid + 256 * i;
                int r = c >> 4, col = (c & 15) * 8;
                cp16(bp + (r * BNNSTR + col) * 2,
                     Bb + (size_t)(k0 + r) * ldb + bn + col);
            }
        }
    };

    float acc[4][4][4] = {};

    auto compute = [&](int st) {
        uint32_t aBase = aU + (uint32_t)(st * HSTG * 2);
        uint32_t bBase = bU + (uint32_t)(st * BSTG * 2);
        const int lrow = lane & 15;
        const int lhalf = lane >> 4;
#pragma unroll
        for (int ks = 0; ks < 4; ks++) {
            const int k0s = ks * 16;
            uint32_t a[4][4];
#pragma unroll
            for (int mt = 0; mt < 4; mt++) {
                int m0 = wm * 64 + mt * 16;
                ldsm4(a[mt], aBase + ((m0 + lrow) * HSTR + k0s + lhalf * 8) * 2);
            }
            uint32_t bf[2][4];
#pragma unroll
            for (int np = 0; np < 2; np++) {
                int n0 = wn * 32 + np * 16;
                if (NT) {
                    ldsm4(bf[np], bBase + ((n0 + lrow) * HSTR + k0s + lhalf * 8) * 2);
                } else {
                    ldsm4t(bf[np], bBase + ((k0s + lrow) * BNNSTR + n0 + lhalf * 8) * 2);
                }
            }
#pragma unroll
            for (int nt = 0; nt < 4; nt++) {
                uint32_t b0, b1;
                if (NT) {
                    b0 = bf[nt >> 1][nt & 1];
                    b1 = bf[nt >> 1][(nt & 1) + 2];
                } else {
                    b0 = bf[nt >> 1][(nt & 1) * 2];
                    b1 = bf[nt >> 1][(nt & 1) * 2 + 1];
                }
#pragma unroll
                for (int mt = 0; mt < 4; mt++)
                    mma16(acc[mt][nt], a[mt], b0, b1);
            }
        }
    };

    const int NI = K / BK;
    issue(0, 0); cp_commit();
    if (NI > 1) { issue(1, BK); cp_commit(); }

    for (int it = 0; it < NI; it++) {
        if (it + 1 < NI) cp_wait<1>(); else cp_wait<0>();
        __syncthreads();
        if (it + 2 < NI) {
            issue((it + 2) % NST, (it + 2) * BK);
            cp_commit();
        }
        compute(it % NST);
    }

    // Epilogue
#pragma unroll
    for (int nt = 0; nt < 4; nt++) {
        int col = bn + wn * 32 + nt * 8 + (lane & 3) * 2;
        float bv0 = 0.f, bv1 = 0.f;
        if (bias) { bv0 = bias[col]; bv1 = bias[col + 1]; }
#pragma unroll
        for (int mt = 0; mt < 4; mt++) {
            int r0 = bm + wm * 64 + mt * 16 + (lane >> 2);
            float v0 = acc[mt][nt][0] * scale + bv0;
            float v1 = acc[mt][nt][1] * scale + bv1;
            float v2 = acc[mt][nt][2] * scale + bv0;
            float v3 = acc[mt][nt][3] * scale + bv1;
            if (do_relu) {
                v0 = fmaxf(v0, 0.f); v1 = fmaxf(v1, 0.f);
                v2 = fmaxf(v2, 0.f); v3 = fmaxf(v3, 0.f);
            }
            if (out_half) {
                __half* Cb = (__half*)Cv + blockIdx.z * sC_;
                __half2 h0 = __floats2half2_rn(v0, v1);
                __half2 h1 = __floats2half2_rn(v2, v3);
                *(__half2*)(Cb + (size_t)r0 * ldc + col) = h0;
                *(__half2*)(Cb + (size_t)(r0 + 8) * ldc + col) = h1;
            } else {
                float* Cb = (float*)Cv + blockIdx.z * sC_;
                *(float2*)(Cb + (size_t)r0 * ldc + col) = make_float2(v0, v1);
                *(float2*)(Cb + (size_t)(r0 + 8) * ldc + col) = make_float2(v2, v3);
            }
        }
    }
}

// ---------------------------------------------------------------------------
// Prep: fp32 -> half elementwise
__global__ __launch_bounds__(256) void cvt_h_kernel(
    const float* __restrict__ x, __half* __restrict__ y)
{
    size_t i = (size_t)blockIdx.x * blockDim.x + threadIdx.x;
    float4 v = ((const float4*)x)[i];
    __half2 a = __floats2half2_rn(v.x, v.y);
    __half2 b = __floats2half2_rn(v.z, v.w);
    uint2 u;
    u.x = *(uint32_t*)&a; u.y = *(uint32_t*)&b;
    ((uint2*)y)[i] = u;
}

// Prep: transpose + convert: WT[n][k] = half(W[k][n])
__global__ __launch_bounds__(256) void transpose_h_kernel(
    const float* __restrict__ W, __half* __restrict__ WT, int Kd, int Nd)
{
    __shared__ float t[32][33];
    const int tx = threadIdx.x & 31, ty = threadIdx.x >> 5;
    const int n0 = blockIdx.x * 32, k0 = blockIdx.y * 32;
#pragma unroll
    for (int i = 0; i < 4; i++)
        t[ty + 8 * i][tx] = W[(size_t)(k0 + ty + 8 * i) * Nd + n0 + tx];
    __syncthreads();
#pragma unroll
    for (int i = 0; i < 4; i++)
        WT[(size_t)(n0 + ty + 8 * i) * Kd + k0 + tx] = __float2half(t[tx][ty + 8 * i]);
}

// rel[b][t*SS+s][h] = half(tanh(skey[b,s,h] + tkey[b,t,h]))
__global__ __launch_bounds__(256) void relkey_kernel(
    const float* __restrict__ skey, const float* __restrict__ tkey,
    __half* __restrict__ rel)
{
    const size_t H4 = HD / 4;
    size_t idx = (size_t)blockIdx.x * blockDim.x + threadIdx.x;
    size_t h4 = idx % H4;
    size_t rest = idx / H4;
    int s = (int)(rest % SS); rest /= SS;
    int t = (int)(rest % TT);
    int b = (int)(rest / TT);
    float4 sv = ((const float4*)skey)[((size_t)b * SS + s) * H4 + h4];
    float4 tv = ((const float4*)tkey)[((size_t)b * TT + t) * H4 + h4];
    __half2 h0 = __floats2half2_rn(tanhf(sv.x + tv.x), tanhf(sv.y + tv.y));
    __half2 h1 = __floats2half2_rn(tanhf(sv.z + tv.z), tanhf(sv.w + tv.w));
    uint2 u; u.x = *(uint32_t*)&h0; u.y = *(uint32_t*)&h1;
    ((uint2*)rel)[idx] = u;
}

// Softmax over 4096 per row: half in, half out, in place. Math in fp32.
__global__ __launch_bounds__(256) void softmax_kernel(__half* __restrict__ data)
{
    __half* row = data + (size_t)blockIdx.x * TSD;
    const int tid = threadIdx.x;
    float v[16];
    float m = -INFINITY;
#pragma unroll
    for (int i = 0; i < 16; i++) {
        v[i] = __half2float(row[tid + i * 256]);
        m = fmaxf(m, v[i]);
    }
#pragma unroll
    for (int o = 16; o; o >>= 1) m = fmaxf(m, __shfl_xor_sync(0xffffffffu, m, o));
    __shared__ float redm[8];
    __shared__ float reds[8];
    if ((tid & 31) == 0) redm[tid >> 5] = m;
    __syncthreads();
#pragma unroll
    for (int w = 0; w < 8; w++) m = fmaxf(m, redm[w]);
    float s = 0.f;
#pragma unroll
    for (int i = 0; i < 16; i++) {
        v[i] = expf(v[i] - m);
        s += v[i];
    }
#pragma unroll
    for (int o = 16; o; o >>= 1) s += __shfl_xor_sync(0xffffffffu, s, o);
    if ((tid & 31) == 0) reds[tid >> 5] = s;
    __syncthreads();
    s = 0.f;
#pragma unroll
    for (int w = 0; w < 8; w++) s += reds[w];
    float inv = 1.f / s;
#pragma unroll
    for (int i = 0; i < 16; i++)
        row[tid + i * 256] = __float2half(v[i] * inv);
}

// x_h[row][:768] = qin_h[row][:]   (uint4 = 16 B = 8 halves per chunk)
__global__ __launch_bounds__(256) void concat_kernel(
    const __half* __restrict__ qh8, __half* __restrict__ x)
{
    const size_t Q8 = QD / 8;   // 96 chunks of 8 halves per row
    size_t idx = (size_t)blockIdx.x * blockDim.x + threadIdx.x;
    size_t rowi = idx / Q8;
    size_t c8 = idx % Q8;
    uint4 u = ((const uint4*)qh8)[idx];
    *(uint4*)(x + rowi * XD + c8 * 8) = u;
}

// ---------------------------------------------------------------------------
extern "C" void kernel_launch(void* const* d_in, const int* in_sizes, int n_in,
                              void* d_out, int out_size)
{
    const float* query = (const float*)d_in[0];
    const float* src   = (const float*)d_in[1];
    const float* trg   = (const float*)d_in[2];
    const float* Wq    = (const float*)d_in[3];
    const float* b_q   = (const float*)d_in[4];
    const float* Ws    = (const float*)d_in[5];
    const float* b_s   = (const float*)d_in[6];
    const float* Wt    = (const float*)d_in[7];
    const float* b_t   = (const float*)d_in[8];
    const float* Wo    = (const float*)d_in[9];
    const float* b_o   = (const float*)d_in[10];
    float* out = (float*)d_out;

    __half *qin_h, *src_h, *trg_h, *wqT, *wsT, *wtT, *woT;
    __half *qh, *relh, *scoresh, *xh;
    float *skey, *tkey;
    cudaGetSymbolAddress((void**)&qin_h, g_qin_h);
    cudaGetSymbolAddress((void**)&src_h, g_src_h);
    cudaGetSymbolAddress((void**)&trg_h, g_trg_h);
    cudaGetSymbolAddress((void**)&wqT, g_wqT);
    cudaGetSymbolAddress((void**)&wsT, g_wsT);
    cudaGetSymbolAddress((void**)&wtT, g_wtT);
    cudaGetSymbolAddress((void**)&woT, g_woT);
    cudaGetSymbolAddress((void**)&qh, g_qh);
    cudaGetSymbolAddress((void**)&skey, g_skey);
    cudaGetSymbolAddress((void**)&tkey, g_tkey);
    cudaGetSymbolAddress((void**)&relh, g_relh);
    cudaGetSymbolAddress((void**)&scoresh, g_scoresh);
    cudaGetSymbolAddress((void**)&xh, g_xh);

    const float inv_sqrt_h = 1.0f / sqrtf((float)HD);
    dim3 blk(256);

    cudaFuncSetAttribute(hgemm<true>,
                         cudaFuncAttributeMaxDynamicSharedMemorySize, SMEM_BYTES);
    cudaFuncSetAttribute(hgemm<false>,
                         cudaFuncAttributeMaxDynamicSharedMemorySize, SMEM_BYTES);

    // 0. prep
    auto cvt = [&](const float* in, __half* outp, size_t n) {
        cvt_h_kernel<<<(unsigned)(n / 4 / 256), blk>>>(in, outp);
    };
    cvt(query, qin_h, (size_t)BB * LL * QD);
    cvt(src,   src_h, (size_t)BB * SS * FD);
    cvt(trg,   trg_h, (size_t)BB * TT * FD);
    transpose_h_kernel<<<dim3(HD / 32, QD / 32), blk>>>(Wq, wqT, QD, HD);
    transpose_h_kernel<<<dim3(HD / 32, FD / 32), blk>>>(Ws, wsT, FD, HD);
    transpose_h_kernel<<<dim3(HD / 32, FD / 32), blk>>>(Wt, wtT, FD, HD);
    transpose_h_kernel<<<dim3(OD / 32, XD / 32), blk>>>(Wo, woT, XD, OD);

    // 1. q = query @ Wq + b_q  -> half
    hgemm<true><<<dim3(HD / 128, (BB * LL) / 128, 1), blk, SMEM_BYTES>>>(
        qin_h, QD, 0, wqT, QD, 0, b_q, qh, HD, 0, QD, 1.f, 0, 1);

    // 2. s_key = src @ Ws + b_s  -> fp32
    hgemm<true><<<dim3(HD / 128, (BB * SS) / 128, 1), blk, SMEM_BYTES>>>(
        src_h, FD, 0, wsT, FD, 0, b_s, skey, HD, 0, FD, 1.f, 0, 0);

    // 3. t_key = trg @ Wt + b_t  -> fp32
    hgemm<true><<<dim3(HD / 128, (BB * TT) / 128, 1), blk, SMEM_BYTES>>>(
        trg_h, FD, 0, wtT, FD, 0, b_t, tkey, HD, 0, FD, 1.f, 0, 0);

    // 4. rel = half(tanh(skey + tkey))
    {
        size_t n4 = (size_t)BB * TSD * HD / 4;
        relkey_kernel<<<(unsigned)(n4 / 256), blk>>>(skey, tkey, relh);
    }

    // 5. scores = q . rel^T / sqrt(H)  -> half directly   [NT]
    hgemm<true><<<dim3(TSD / 128, LL / 128, BB), blk, SMEM_BYTES>>>(
        qh, HD, (size_t)LL * HD,
        relh, HD, (size_t)TSD * HD,
        nullptr,
        scoresh, TSD, (size_t)LL * TSD,
        HD, inv_sqrt_h, 0, 1);

    // 6. softmax in place on half
    softmax_kernel<<<BB * LL, blk>>>(scoresh);

    // 7. x_h[:, :768] = qin_h (half copy, uint4 chunks)
    {
        size_t n8 = (size_t)BB * LL * QD / 8;
        concat_kernel<<<(unsigned)(n8 / 256), blk>>>(qin_h, xh);
    }

    // 8. x_h[:, 768:] = scores @ rel  -> half   [NN]
    hgemm<false><<<dim3(HD / 128, LL / 128, BB), blk, SMEM_BYTES>>>(
        scoresh, TSD, (size_t)LL * TSD,
        relh, HD, (size_t)TSD * HD,
        nullptr,
        xh + QD, XD, (size_t)LL * XD,
        TSD, 1.f, 0, 1);

    // 9. out = relu(x @ Wo + b_o) -> fp32
    hgemm<true><<<dim3(OD / 128, (BB * LL) / 128, 1), blk, SMEM_BYTES>>>(
        xh, XD, 0, woT, XD, 0, b_o, out, OD, 0, XD, 1.f, 1, 0);
}

// round 12
// speedup vs baseline: 2.8047x; 1.0066x over previous
#include <cuda_runtime.h>
#include <cuda_fp16.h>
#include <math.h>
#include <stdint.h>

// Problem dims
constexpr int BB = 32;
constexpr int LL = 256;
constexpr int SS = 64;
constexpr int TT = 64;
constexpr int QD = 768;
constexpr int FD = 1024;
constexpr int HD = 768;
constexpr int OD = 768;
constexpr int TSD = TT * SS;
constexpr int XD = QD + HD;

// Scratch (static device globals).
// src/trg, Ws/Wt, skey/tkey are paired contiguously for z=2 batched GEMM.
__device__ __align__(16) __half g_qin_h[(size_t)BB * LL * QD];
__device__ __align__(16) __half g_st_h[2 * (size_t)BB * SS * FD];   // [src|trg]
__device__ __align__(16) __half g_wqT[(size_t)HD * QD];             // [n][k]
__device__ __align__(16) __half g_wstT[2 * (size_t)HD * FD];        // [Ws|Wt] T
__device__ __align__(16) __half g_woT[(size_t)OD * XD];
__device__ __align__(16) __half g_qh[(size_t)BB * LL * HD];
__device__ __align__(16) float  g_stkey[2 * (size_t)BB * SS * HD];  // [skey|tkey]
__device__ __align__(16) __half g_relh[(size_t)BB * TSD * HD];      // [b][ts][h]
__device__ __align__(16) __half g_scoresh[(size_t)BB * LL * TSD];
__device__ __align__(16) __half g_xh[(size_t)BB * LL * XD];

__device__ __forceinline__ void cp16(uint32_t dst_smem, const void* src) {
    asm volatile("cp.async.cg.shared.global [%0], [%1], 16;\n"
                 :: "r"(dst_smem), "l"(src));
}
__device__ __forceinline__ void cp_commit() {
    asm volatile("cp.async.commit_group;\n");
}
template <int N>
__device__ __forceinline__ void cp_wait() {
    asm volatile("cp.async.wait_group %0;\n" :: "n"(N));
}

__device__ __forceinline__ void ldsm4(uint32_t* r, uint32_t addr) {
    asm volatile("ldmatrix.sync.aligned.m8n8.x4.shared.b16 {%0,%1,%2,%3}, [%4];"
                 : "=r"(r[0]), "=r"(r[1]), "=r"(r[2]), "=r"(r[3]) : "r"(addr));
}
__device__ __forceinline__ void ldsm4t(uint32_t* r, uint32_t addr) {
    asm volatile("ldmatrix.sync.aligned.m8n8.x4.trans.shared.b16 {%0,%1,%2,%3}, [%4];"
                 : "=r"(r[0]), "=r"(r[1]), "=r"(r[2]), "=r"(r[3]) : "r"(addr));
}

__device__ __forceinline__ void mma16(float* c, const uint32_t* a,
                                      uint32_t b0, uint32_t b1) {
    asm volatile(
        "mma.sync.aligned.m16n8k16.row.col.f32.f16.f16.f32 "
        "{%0,%1,%2,%3}, {%4,%5,%6,%7}, {%8,%9}, {%0,%1,%2,%3};"
        : "+f"(c[0]), "+f"(c[1]), "+f"(c[2]), "+f"(c[3])
        : "r"(a[0]), "r"(a[1]), "r"(a[2]), "r"(a[3]), "r"(b0), "r"(b1));
}

// ===========================================================================
// FP16 tensor-core GEMM, BK=64, 3-stage cp.async ring, one sync per iter.
// EXACT R10 mainloop (proven at 647us). bias2: per-z bias select (z=1 ->
// bias2) for the merged projection launch; batched GEMMs pass null/null.
// ===========================================================================
constexpr int NST  = 3;
constexpr int BK   = 64;
constexpr int HSTR = 72;
constexpr int HSTG = 128 * HSTR;
constexpr int BNNSTR = 136;
constexpr int BNNSTG = 64 * BNNSTR;
constexpr int SMEM_BYTES = NST * (HSTG + HSTG) * 2;   // 110592 B

template <bool NT>
__global__ __launch_bounds__(256) void hgemm(
    const __half* __restrict__ A, int lda, size_t sA_,
    const __half* __restrict__ B, int ldb, size_t sB_,
    const float* __restrict__ bias, const float* __restrict__ bias2,
    void* __restrict__ Cv, int ldc, size_t sC_,
    int K, float scale, int do_relu, int out_half)
{
    extern __shared__ __half smh[];
    __half* sA = smh;
    __half* sB = smh + NST * HSTG;
    constexpr int BSTG = NT ? HSTG : BNNSTG;

    const __half* Ab = A + blockIdx.z * sA_;
    const __half* Bb = B + blockIdx.z * sB_;
    const float* biasz = (blockIdx.z == 1 && bias2) ? bias2 : bias;

    const int tid  = threadIdx.x;
    const int lane = tid & 31;
    const int wid  = tid >> 5;
    const int wm   = wid & 1;
    const int wn   = wid >> 1;
    const int bm   = blockIdx.y * 128;
    const int bn   = blockIdx.x * 128;

    const uint32_t aU = (uint32_t)__cvta_generic_to_shared(sA);
    const uint32_t bU = (uint32_t)__cvta_generic_to_shared(sB);

    auto issue = [&](int st, int k0) {
        uint32_t ap = aU + (uint32_t)(st * HSTG * 2);
#pragma unroll
        for (int i = 0; i < 4; i++) {
            int c = tid + 256 * i;
            int r = c >> 3, col = (c & 7) * 8;
            cp16(ap + (r * HSTR + col) * 2, Ab + (size_t)(bm + r) * lda + k0 + col);
        }
        uint32_t bp = bU + (uint32_t)(st * BSTG * 2);
        if (NT) {
#pragma unroll
            for (int i = 0; i < 4; i++) {
                int c = tid + 256 * i;
                int r = c >> 3, col = (c & 7) * 8;
                cp16(bp + (r * HSTR + col) * 2, Bb + (size_t)(bn + r) * ldb + k0 + col);
            }
        } else {
#pragma unroll
            for (int i = 0; i < 4; i++) {
                int c = tid + 256 * i;
                int r = c >> 4, col = (c & 15) * 8;
                cp16(bp + (r * BNNSTR + col) * 2,
                     Bb + (size_t)(k0 + r) * ldb + bn + col);
            }
        }
    };

    float acc[4][4][4] = {};

    auto compute = [&](int st) {
        uint32_t aBase = aU + (uint32_t)(st * HSTG * 2);
        uint32_t bBase = bU + (uint32_t)(st * BSTG * 2);
        const int lrow = lane & 15;
        const int lhalf = lane >> 4;
#pragma unroll
        for (int ks = 0; ks < 4; ks++) {
            const int k0s = ks * 16;
            uint32_t a[4][4];
#pragma unroll
            for (int mt = 0; mt < 4; mt++) {
                int m0 = wm * 64 + mt * 16;
                ldsm4(a[mt], aBase + ((m0 + lrow) * HSTR + k0s + lhalf * 8) * 2);
            }
            uint32_t bf[2][4];
#pragma unroll
            for (int np = 0; np < 2; np++) {
                int n0 = wn * 32 + np * 16;
                if (NT) {
                    ldsm4(bf[np], bBase + ((n0 + lrow) * HSTR + k0s + lhalf * 8) * 2);
                } else {
                    ldsm4t(bf[np], bBase + ((k0s + lrow) * BNNSTR + n0 + lhalf * 8) * 2);
                }
            }
#pragma unroll
            for (int nt = 0; nt < 4; nt++) {
                uint32_t b0, b1;
                if (NT) {
                    b0 = bf[nt >> 1][nt & 1];
                    b1 = bf[nt >> 1][(nt & 1) + 2];
                } else {
                    b0 = bf[nt >> 1][(nt & 1) * 2];
                    b1 = bf[nt >> 1][(nt & 1) * 2 + 1];
                }
#pragma unroll
                for (int mt = 0; mt < 4; mt++)
                    mma16(acc[mt][nt], a[mt], b0, b1);
            }
        }
    };

    const int NI = K / BK;
    issue(0, 0); cp_commit();
    if (NI > 1) { issue(1, BK); cp_commit(); }

    for (int it = 0; it < NI; it++) {
        if (it + 1 < NI) cp_wait<1>(); else cp_wait<0>();
        __syncthreads();
        if (it + 2 < NI) {
            issue((it + 2) % NST, (it + 2) * BK);
            cp_commit();
        }
        compute(it % NST);
    }

    // Epilogue
#pragma unroll
    for (int nt = 0; nt < 4; nt++) {
        int col = bn + wn * 32 + nt * 8 + (lane & 3) * 2;
        float bv0 = 0.f, bv1 = 0.f;
        if (biasz) { bv0 = biasz[col]; bv1 = biasz[col + 1]; }
#pragma unroll
        for (int mt = 0; mt < 4; mt++) {
            int r0 = bm + wm * 64 + mt * 16 + (lane >> 2);
            float v0 = acc[mt][nt][0] * scale + bv0;
            float v1 = acc[mt][nt][1] * scale + bv1;
            float v2 = acc[mt][nt][2] * scale + bv0;
            float v3 = acc[mt][nt][3] * scale + bv1;
            if (do_relu) {
                v0 = fmaxf(v0, 0.f); v1 = fmaxf(v1, 0.f);
                v2 = fmaxf(v2, 0.f); v3 = fmaxf(v3, 0.f);
            }
            if (out_half) {
                __half* Cb = (__half*)Cv + blockIdx.z * sC_;
                __half2 h0 = __floats2half2_rn(v0, v1);
                __half2 h1 = __floats2half2_rn(v2, v3);
                *(__half2*)(Cb + (size_t)r0 * ldc + col) = h0;
                *(__half2*)(Cb + (size_t)(r0 + 8) * ldc + col) = h1;
            } else {
                float* Cb = (float*)Cv + blockIdx.z * sC_;
                *(float2*)(Cb + (size_t)r0 * ldc + col) = make_float2(v0, v1);
                *(float2*)(Cb + (size_t)(r0 + 8) * ldc + col) = make_float2(v2, v3);
            }
        }
    }
}

// ---------------------------------------------------------------------------
// Fused prep: fp32 -> half for query, src, trg in ONE launch.
// Chunk = 4 floats (uint2 out). Ranges: [0,C1) query, [C1,C1+C2) src,
// [C1+C2, C1+2*C2) trg.
constexpr size_t CVT_C1 = (size_t)BB * LL * QD / 4;   // 1572864
constexpr size_t CVT_C2 = (size_t)BB * SS * FD / 4;   // 524288
constexpr size_t CVT_TOT = CVT_C1 + 2 * CVT_C2;       // 2621440

__global__ __launch_bounds__(256) void cvt_all_kernel(
    const float* __restrict__ query, const float* __restrict__ src,
    const float* __restrict__ trg,
    __half* __restrict__ qin_h, __half* __restrict__ st_h)
{
    size_t i = (size_t)blockIdx.x * blockDim.x + threadIdx.x;
    const float* sp;
    __half* dp;
    size_t off;
    if (i < CVT_C1)            { sp = query; dp = qin_h; off = i; }
    else if (i < CVT_C1 + CVT_C2) { sp = src; dp = st_h; off = i - CVT_C1; }
    else                       { sp = trg; dp = st_h + (size_t)BB * SS * FD;
                                 off = i - CVT_C1 - CVT_C2; }
    float4 v = ((const float4*)sp)[off];
    __half2 a = __floats2half2_rn(v.x, v.y);
    __half2 b = __floats2half2_rn(v.z, v.w);
    uint2 u;
    u.x = *(uint32_t*)&a; u.y = *(uint32_t*)&b;
    ((uint2*)dp)[off] = u;
}

// Fused transpose+convert for all 4 weights: WT[n][k] = half(W[k][n]).
// grid (24, 48, 4): z selects matrix; early-exit when k0 >= Kd[z].
// z=0: Wq (K=768), z=1: Ws (K=1024), z=2: Wt (K=1024), z=3: Wo (K=1536).
// All have Nd = 768.
__global__ __launch_bounds__(256) void transpose_all_kernel(
    const float* __restrict__ Wq, const float* __restrict__ Ws,
    const float* __restrict__ Wt, const float* __restrict__ Wo,
    __half* __restrict__ wqT, __half* __restrict__ wstT,
    __half* __restrict__ woT)
{
    const int z = blockIdx.z;
    int Kd;
    const float* W;
    __half* WT;
    if (z == 0)      { Kd = QD; W = Wq; WT = wqT; }
    else if (z == 1) { Kd = FD; W = Ws; WT = wstT; }
    else if (z == 2) { Kd = FD; W = Wt; WT = wstT + (size_t)HD * FD; }
    else             { Kd = XD; W = Wo; WT = woT; }
    const int k0 = blockIdx.y * 32;
    if (k0 >= Kd) return;
    const int Nd = HD;   // all weight matrices have 768 output cols
    __shared__ float t[32][33];
    const int tx = threadIdx.x & 31, ty = threadIdx.x >> 5;
    const int n0 = blockIdx.x * 32;
#pragma unroll
    for (int i = 0; i < 4; i++)
        t[ty + 8 * i][tx] = W[(size_t)(k0 + ty + 8 * i) * Nd + n0 + tx];
    __syncthreads();
#pragma unroll
    for (int i = 0; i < 4; i++)
        WT[(size_t)(n0 + ty + 8 * i) * Kd + k0 + tx] = __float2half(t[tx][ty + 8 * i]);
}

// rel[b][t*SS+s][h] = half(tanh(skey[b,s,h] + tkey[b,t,h]))
__global__ __launch_bounds__(256) void relkey_kernel(
    const float* __restrict__ skey, const float* __restrict__ tkey,
    __half* __restrict__ rel)
{
    const size_t H4 = HD / 4;
    size_t idx = (size_t)blockIdx.x * blockDim.x + threadIdx.x;
    size_t h4 = idx % H4;
    size_t rest = idx / H4;
    int s = (int)(rest % SS); rest /= SS;
    int t = (int)(rest % TT);
    int b = (int)(rest / TT);
    float4 sv = ((const float4*)skey)[((size_t)b * SS + s) * H4 + h4];
    float4 tv = ((const float4*)tkey)[((size_t)b * TT + t) * H4 + h4];
    __half2 h0 = __floats2half2_rn(tanhf(sv.x + tv.x), tanhf(sv.y + tv.y));
    __half2 h1 = __floats2half2_rn(tanhf(sv.z + tv.z), tanhf(sv.w + tv.w));
    uint2 u; u.x = *(uint32_t*)&h0; u.y = *(uint32_t*)&h1;
    ((uint2*)rel)[idx] = u;
}

// Softmax over 4096 per row: half in, half out, in place. Math in fp32.
__global__ __launch_bounds__(256) void softmax_kernel(__half* __restrict__ data)
{
    __half* row = data + (size_t)blockIdx.x * TSD;
    const int tid = threadIdx.x;
    float v[16];
    float m = -INFINITY;
#pragma unroll
    for (int i = 0; i < 16; i++) {
        v[i] = __half2float(row[tid + i * 256]);
        m = fmaxf(m, v[i]);
    }
#pragma unroll
    for (int o = 16; o; o >>= 1) m = fmaxf(m, __shfl_xor_sync(0xffffffffu, m, o));
    __shared__ float redm[8];
    __shared__ float reds[8];
    if ((tid & 31) == 0) redm[tid >> 5] = m;
    __syncthreads();
#pragma unroll
    for (int w = 0; w < 8; w++) m = fmaxf(m, redm[w]);
    float s = 0.f;
#pragma unroll
    for (int i = 0; i < 16; i++) {
        v[i] = expf(v[i] - m);
        s += v[i];
    }
#pragma unroll
    for (int o = 16; o; o >>= 1) s += __shfl_xor_sync(0xffffffffu, s, o);
    if ((tid & 31) == 0) reds[tid >> 5] = s;
    __syncthreads();
    s = 0.f;
#pragma unroll
    for (int w = 0; w < 8; w++) s += reds[w];
    float inv = 1.f / s;
#pragma unroll
    for (int i = 0; i < 16; i++)
        row[tid + i * 256] = __float2half(v[i] * inv);
}

// x_h[row][:768] = qin_h[row][:]   (uint4 = 16 B = 8 halves per chunk)
__global__ __launch_bounds__(256) void concat_kernel(
    const __half* __restrict__ qh8, __half* __restrict__ x)
{
    const size_t Q8 = QD / 8;
    size_t idx = (size_t)blockIdx.x * blockDim.x + threadIdx.x;
    size_t rowi = idx / Q8;
    size_t c8 = idx % Q8;
    uint4 u = ((const uint4*)qh8)[idx];
    *(uint4*)(x + rowi * XD + c8 * 8) = u;
}

// ---------------------------------------------------------------------------
extern "C" void kernel_launch(void* const* d_in, const int* in_sizes, int n_in,
                              void* d_out, int out_size)
{
    const float* query = (const float*)d_in[0];
    const float* src   = (const float*)d_in[1];
    const float* trg   = (const float*)d_in[2];
    const float* Wq    = (const float*)d_in[3];
    const float* b_q   = (const float*)d_in[4];
    const float* Ws    = (const float*)d_in[5];
    const float* b_s   = (const float*)d_in[6];
    const float* Wt    = (const float*)d_in[7];
    const float* b_t   = (const float*)d_in[8];
    const float* Wo    = (const float*)d_in[9];
    const float* b_o   = (const float*)d_in[10];
    float* out = (float*)d_out;

    __half *qin_h, *st_h, *wqT, *wstT, *woT, *qh, *relh, *scoresh, *xh;
    float *stkey;
    cudaGetSymbolAddress((void**)&qin_h, g_qin_h);
    cudaGetSymbolAddress((void**)&st_h, g_st_h);
    cudaGetSymbolAddress((void**)&wqT, g_wqT);
    cudaGetSymbolAddress((void**)&wstT, g_wstT);
    cudaGetSymbolAddress((void**)&woT, g_woT);
    cudaGetSymbolAddress((void**)&qh, g_qh);
    cudaGetSymbolAddress((void**)&stkey, g_stkey);
    cudaGetSymbolAddress((void**)&relh, g_relh);
    cudaGetSymbolAddress((void**)&scoresh, g_scoresh);
    cudaGetSymbolAddress((void**)&xh, g_xh);

    const float inv_sqrt_h = 1.0f / sqrtf((float)HD);
    dim3 blk(256);

    cudaFuncSetAttribute(hgemm<true>,
                         cudaFuncAttributeMaxDynamicSharedMemorySize, SMEM_BYTES);
    cudaFuncSetAttribute(hgemm<false>,
                         cudaFuncAttributeMaxDynamicSharedMemorySize, SMEM_BYTES);

    // 0a. fused input conversion (query, src, trg -> half)
    cvt_all_kernel<<<(unsigned)(CVT_TOT / 256), blk>>>(
        query, src, trg, qin_h, st_h);
    // 0b. fused weight transpose+convert (Wq, Ws, Wt, Wo)
    transpose_all_kernel<<<dim3(HD / 32, XD / 32, 4), blk>>>(
        Wq, Ws, Wt, Wo, wqT, wstT, woT);

    // 1. q = query @ Wq + b_q  -> half
    hgemm<true><<<dim3(HD / 128, (BB * LL) / 128, 1), blk, SMEM_BYTES>>>(
        qin_h, QD, 0, wqT, QD, 0, b_q, nullptr, qh, HD, 0, QD, 1.f, 0, 1);

    // 2+3. [skey|tkey] = [src|trg] @ [Ws|Wt] + [b_s|b_t]  (z=2 merged)
    hgemm<true><<<dim3(HD / 128, (BB * SS) / 128, 2), blk, SMEM_BYTES>>>(
        st_h, FD, (size_t)BB * SS * FD,
        wstT, FD, (size_t)HD * FD,
        b_s, b_t,
        stkey, HD, (size_t)BB * SS * HD,
        FD, 1.f, 0, 0);

    // 4. rel = half(tanh(skey + tkey))
    {
        size_t n4 = (size_t)BB * TSD * HD / 4;
        relkey_kernel<<<(unsigned)(n4 / 256), blk>>>(
            stkey, stkey + (size_t)BB * SS * HD, relh);
    }

    // 5. scores = q . rel^T / sqrt(H)  -> half   [NT]
    hgemm<true><<<dim3(TSD / 128, LL / 128, BB), blk, SMEM_BYTES>>>(
        qh, HD, (size_t)LL * HD,
        relh, HD, (size_t)TSD * HD,
        nullptr, nullptr,
        scoresh, TSD, (size_t)LL * TSD,
        HD, inv_sqrt_h, 0, 1);

    // 6. softmax in place on half
    softmax_kernel<<<BB * LL, blk>>>(scoresh);

    // 7. x_h[:, :768] = qin_h
    {
        size_t n8 = (size_t)BB * LL * QD / 8;
        concat_kernel<<<(unsigned)(n8 / 256), blk>>>(qin_h, xh);
    }

    // 8. x_h[:, 768:] = scores @ rel  -> half   [NN]
    hgemm<false><<<dim3(HD / 128, LL / 128, BB), blk, SMEM_BYTES>>>(
        scoresh, TSD, (size_t)LL * TSD,
        relh, HD, (size_t)TSD * HD,
        nullptr, nullptr,
        xh + QD, XD, (size_t)LL * XD,
        TSD, 1.f, 0, 1);

    // 9. out = relu(x @ Wo + b_o) -> fp32
    hgemm<true><<<dim3(OD / 128, (BB * LL) / 128, 1), blk, SMEM_BYTES>>>(
        xh, XD, 0, woT, XD, 0, b_o, nullptr, out, OD, 0, XD, 1.f, 1, 0);
}

// round 13
// speedup vs baseline: 2.9062x; 1.0362x over previous
#include <cuda_runtime.h>
#include <cuda_fp16.h>
#include <math.h>
#include <stdint.h>

// Problem dims
constexpr int BB = 32;
constexpr int LL = 256;
constexpr int SS = 64;
constexpr int TT = 64;
constexpr int QD = 768;
constexpr int FD = 1024;
constexpr int HD = 768;
constexpr int OD = 768;
constexpr int TSD = TT * SS;
constexpr int XD = QD + HD;

// Scratch (static device globals).
__device__ __align__(16) __half g_qin_h[(size_t)BB * LL * QD];
__device__ __align__(16) __half g_st_h[2 * (size_t)BB * SS * FD];   // [src|trg]
__device__ __align__(16) __half g_wqT[(size_t)HD * QD];             // [n][k]
__device__ __align__(16) __half g_wstT[2 * (size_t)HD * FD];        // [Ws|Wt] T
__device__ __align__(16) __half g_woT[(size_t)OD * XD];
__device__ __align__(16) __half g_qh[(size_t)BB * LL * HD];
__device__ __align__(16) float  g_stkey[2 * (size_t)BB * SS * HD];  // [skey|tkey]
__device__ __align__(16) __half g_relh[(size_t)BB * TSD * HD];      // [b][ts][h]
__device__ __align__(16) __half g_scoresh[(size_t)BB * LL * TSD];
__device__ __align__(16) __half g_xh[(size_t)BB * LL * XD];

__device__ __forceinline__ void cp16(uint32_t dst_smem, const void* src) {
    asm volatile("cp.async.cg.shared.global [%0], [%1], 16;\n"
                 :: "r"(dst_smem), "l"(src));
}
__device__ __forceinline__ void cp_commit() {
    asm volatile("cp.async.commit_group;\n");
}
template <int N>
__device__ __forceinline__ void cp_wait() {
    asm volatile("cp.async.wait_group %0;\n" :: "n"(N));
}

__device__ __forceinline__ void ldsm4(uint32_t* r, uint32_t addr) {
    asm volatile("ldmatrix.sync.aligned.m8n8.x4.shared.b16 {%0,%1,%2,%3}, [%4];"
                 : "=r"(r[0]), "=r"(r[1]), "=r"(r[2]), "=r"(r[3]) : "r"(addr));
}
__device__ __forceinline__ void ldsm4t(uint32_t* r, uint32_t addr) {
    asm volatile("ldmatrix.sync.aligned.m8n8.x4.trans.shared.b16 {%0,%1,%2,%3}, [%4];"
                 : "=r"(r[0]), "=r"(r[1]), "=r"(r[2]), "=r"(r[3]) : "r"(addr));
}

__device__ __forceinline__ void mma16(float* c, const uint32_t* a,
                                      uint32_t b0, uint32_t b1) {
    asm volatile(
        "mma.sync.aligned.m16n8k16.row.col.f32.f16.f16.f32 "
        "{%0,%1,%2,%3}, {%4,%5,%6,%7}, {%8,%9}, {%0,%1,%2,%3};"
        : "+f"(c[0]), "+f"(c[1]), "+f"(c[2]), "+f"(c[3])
        : "r"(a[0]), "r"(a[1]), "r"(a[2]), "r"(a[3]), "r"(b0), "r"(b1));
}

// ===========================================================================
// FP16 tensor-core GEMM, BK=64, 2-stage cp.async double buffer, one sync
// per iter. 73.7 KB smem -> 2 CTAs/SM (cross-CTA latency hiding).
// Safety: the sync at top of iter `it` guarantees all warps finished
// compute(it-1); issuing into stage (it+1)&1 == (it-1)&1 is then safe.
// Arithmetic identical to the R10/R11 mainloop (proven, 647/643 us).
// ===========================================================================
constexpr int NST  = 2;
constexpr int BK   = 64;
constexpr int HSTR = 72;
constexpr int HSTG = 128 * HSTR;
constexpr int BNNSTR = 136;
constexpr int BNNSTG = 64 * BNNSTR;
constexpr int SMEM_BYTES = NST * (HSTG + HSTG) * 2;   // 73728 B

template <bool NT>
__global__ __launch_bounds__(256) void hgemm(
    const __half* __restrict__ A, int lda, size_t sA_,
    const __half* __restrict__ B, int ldb, size_t sB_,
    const float* __restrict__ bias, const float* __restrict__ bias2,
    void* __restrict__ Cv, int ldc, size_t sC_,
    int K, float scale, int do_relu, int out_half)
{
    extern __shared__ __half smh[];
    __half* sA = smh;
    __half* sB = smh + NST * HSTG;
    constexpr int BSTG = NT ? HSTG : BNNSTG;

    const __half* Ab = A + blockIdx.z * sA_;
    const __half* Bb = B + blockIdx.z * sB_;
    const float* biasz = (blockIdx.z == 1 && bias2) ? bias2 : bias;

    const int tid  = threadIdx.x;
    const int lane = tid & 31;
    const int wid  = tid >> 5;
    const int wm   = wid & 1;
    const int wn   = wid >> 1;
    const int bm   = blockIdx.y * 128;
    const int bn   = blockIdx.x * 128;

    const uint32_t aU = (uint32_t)__cvta_generic_to_shared(sA);
    const uint32_t bU = (uint32_t)__cvta_generic_to_shared(sB);

    auto issue = [&](int st, int k0) {
        uint32_t ap = aU + (uint32_t)(st * HSTG * 2);
#pragma unroll
        for (int i = 0; i < 4; i++) {
            int c = tid + 256 * i;
            int r = c >> 3, col = (c & 7) * 8;
            cp16(ap + (r * HSTR + col) * 2, Ab + (size_t)(bm + r) * lda + k0 + col);
        }
        uint32_t bp = bU + (uint32_t)(st * BSTG * 2);
        if (NT) {
#pragma unroll
            for (int i = 0; i < 4; i++) {
                int c = tid + 256 * i;
                int r = c >> 3, col = (c & 7) * 8;
                cp16(bp + (r * HSTR + col) * 2, Bb + (size_t)(bn + r) * ldb + k0 + col);
            }
        } else {
#pragma unroll
            for (int i = 0; i < 4; i++) {
                int c = tid + 256 * i;
                int r = c >> 4, col = (c & 15) * 8;
                cp16(bp + (r * BNNSTR + col) * 2,
                     Bb + (size_t)(k0 + r) * ldb + bn + col);
            }
        }
    };

    float acc[4][4][4] = {};

    auto compute = [&](int st) {
        uint32_t aBase = aU + (uint32_t)(st * HSTG * 2);
        uint32_t bBase = bU + (uint32_t)(st * BSTG * 2);
        const int lrow = lane & 15;
        const int lhalf = lane >> 4;
#pragma unroll
        for (int ks = 0; ks < 4; ks++) {
            const int k0s = ks * 16;
            uint32_t a[4][4];
#pragma unroll
            for (int mt = 0; mt < 4; mt++) {
                int m0 = wm * 64 + mt * 16;
                ldsm4(a[mt], aBase + ((m0 + lrow) * HSTR + k0s + lhalf * 8) * 2);
            }
            uint32_t bf[2][4];
#pragma unroll
            for (int np = 0; np < 2; np++) {
                int n0 = wn * 32 + np * 16;
                if (NT) {
                    ldsm4(bf[np], bBase + ((n0 + lrow) * HSTR + k0s + lhalf * 8) * 2);
                } else {
                    ldsm4t(bf[np], bBase + ((k0s + lrow) * BNNSTR + n0 + lhalf * 8) * 2);
                }
            }
#pragma unroll
            for (int nt = 0; nt < 4; nt++) {
                uint32_t b0, b1;
                if (NT) {
                    b0 = bf[nt >> 1][nt & 1];
                    b1 = bf[nt >> 1][(nt & 1) + 2];
                } else {
                    b0 = bf[nt >> 1][(nt & 1) * 2];
                    b1 = bf[nt >> 1][(nt & 1) * 2 + 1];
                }
#pragma unroll
                for (int mt = 0; mt < 4; mt++)
                    mma16(acc[mt][nt], a[mt], b0, b1);
            }
        }
    };

    const int NI = K / BK;
    issue(0, 0); cp_commit();

    for (int it = 0; it < NI; it++) {
        cp_wait<0>();
        __syncthreads();
        if (it + 1 < NI) {
            issue((it + 1) & 1, (it + 1) * BK);
            cp_commit();
        }
        compute(it & 1);
    }

    // Epilogue
#pragma unroll
    for (int nt = 0; nt < 4; nt++) {
        int col = bn + wn * 32 + nt * 8 + (lane & 3) * 2;
        float bv0 = 0.f, bv1 = 0.f;
        if (biasz) { bv0 = biasz[col]; bv1 = biasz[col + 1]; }
#pragma unroll
        for (int mt = 0; mt < 4; mt++) {
            int r0 = bm + wm * 64 + mt * 16 + (lane >> 2);
            float v0 = acc[mt][nt][0] * scale + bv0;
            float v1 = acc[mt][nt][1] * scale + bv1;
            float v2 = acc[mt][nt][2] * scale + bv0;
            float v3 = acc[mt][nt][3] * scale + bv1;
            if (do_relu) {
                v0 = fmaxf(v0, 0.f); v1 = fmaxf(v1, 0.f);
                v2 = fmaxf(v2, 0.f); v3 = fmaxf(v3, 0.f);
            }
            if (out_half) {
                __half* Cb = (__half*)Cv + blockIdx.z * sC_;
                __half2 h0 = __floats2half2_rn(v0, v1);
                __half2 h1 = __floats2half2_rn(v2, v3);
                *(__half2*)(Cb + (size_t)r0 * ldc + col) = h0;
                *(__half2*)(Cb + (size_t)(r0 + 8) * ldc + col) = h1;
            } else {
                float* Cb = (float*)Cv + blockIdx.z * sC_;
                *(float2*)(Cb + (size_t)r0 * ldc + col) = make_float2(v0, v1);
                *(float2*)(Cb + (size_t)(r0 + 8) * ldc + col) = make_float2(v2, v3);
            }
        }
    }
}

// ---------------------------------------------------------------------------
// Fused prep: fp32 -> half for query, src, trg in ONE launch.
constexpr size_t CVT_C1 = (size_t)BB * LL * QD / 4;
constexpr size_t CVT_C2 = (size_t)BB * SS * FD / 4;
constexpr size_t CVT_TOT = CVT_C1 + 2 * CVT_C2;

__global__ __launch_bounds__(256) void cvt_all_kernel(
    const float* __restrict__ query, const float* __restrict__ src,
    const float* __restrict__ trg,
    __half* __restrict__ qin_h, __half* __restrict__ st_h)
{
    size_t i = (size_t)blockIdx.x * blockDim.x + threadIdx.x;
    const float* sp;
    __half* dp;
    size_t off;
    if (i < CVT_C1)            { sp = query; dp = qin_h; off = i; }
    else if (i < CVT_C1 + CVT_C2) { sp = src; dp = st_h; off = i - CVT_C1; }
    else                       { sp = trg; dp = st_h + (size_t)BB * SS * FD;
                                 off = i - CVT_C1 - CVT_C2; }
    float4 v = ((const float4*)sp)[off];
    __half2 a = __floats2half2_rn(v.x, v.y);
    __half2 b = __floats2half2_rn(v.z, v.w);
    uint2 u;
    u.x = *(uint32_t*)&a; u.y = *(uint32_t*)&b;
    ((uint2*)dp)[off] = u;
}

// Fused transpose+convert for all 4 weights: WT[n][k] = half(W[k][n]).
__global__ __launch_bounds__(256) void transpose_all_kernel(
    const float* __restrict__ Wq, const float* __restrict__ Ws,
    const float* __restrict__ Wt, const float* __restrict__ Wo,
    __half* __restrict__ wqT, __half* __restrict__ wstT,
    __half* __restrict__ woT)
{
    const int z = blockIdx.z;
    int Kd;
    const float* W;
    __half* WT;
    if (z == 0)      { Kd = QD; W = Wq; WT = wqT; }
    else if (z == 1) { Kd = FD; W = Ws; WT = wstT; }
    else if (z == 2) { Kd = FD; W = Wt; WT = wstT + (size_t)HD * FD; }
    else             { Kd = XD; W = Wo; WT = woT; }
    const int k0 = blockIdx.y * 32;
    if (k0 >= Kd) return;
    const int Nd = HD;
    __shared__ float t[32][33];
    const int tx = threadIdx.x & 31, ty = threadIdx.x >> 5;
    const int n0 = blockIdx.x * 32;
#pragma unroll
    for (int i = 0; i < 4; i++)
        t[ty + 8 * i][tx] = W[(size_t)(k0 + ty + 8 * i) * Nd + n0 + tx];
    __syncthreads();
#pragma unroll
    for (int i = 0; i < 4; i++)
        WT[(size_t)(n0 + ty + 8 * i) * Kd + k0 + tx] = __float2half(t[tx][ty + 8 * i]);
}

// rel[b][t*SS+s][h] = tanh.approx.f16x2(half2(skey + tkey))
__global__ __launch_bounds__(256) void relkey_kernel(
    const float* __restrict__ skey, const float* __restrict__ tkey,
    __half* __restrict__ rel)
{
    const size_t H4 = HD / 4;
    size_t idx = (size_t)blockIdx.x * blockDim.x + threadIdx.x;
    size_t h4 = idx % H4;
    size_t rest = idx / H4;
    int s = (int)(rest % SS); rest /= SS;
    int t = (int)(rest % TT);
    int b = (int)(rest / TT);
    float4 sv = ((const float4*)skey)[((size_t)b * SS + s) * H4 + h4];
    float4 tv = ((const float4*)tkey)[((size_t)b * TT + t) * H4 + h4];
    __half2 x0 = __floats2half2_rn(sv.x + tv.x, sv.y + tv.y);
    __half2 x1 = __floats2half2_rn(sv.z + tv.z, sv.w + tv.w);
    uint32_t u0 = *(uint32_t*)&x0, u1 = *(uint32_t*)&x1;
    uint32_t r0, r1;
    asm("tanh.approx.f16x2 %0, %1;" : "=r"(r0) : "r"(u0));
    asm("tanh.approx.f16x2 %0, %1;" : "=r"(r1) : "r"(u1));
    uint2 u; u.x = r0; u.y = r1;
    ((uint2*)rel)[idx] = u;
}

// Softmax over 4096 per row: half in/out, in place. Math in fp32.
__global__ __launch_bounds__(256) void softmax_kernel(__half* __restrict__ data)
{
    __half* row = data + (size_t)blockIdx.x * TSD;
    const int tid = threadIdx.x;
    float v[16];
    float m = -INFINITY;
#pragma unroll
    for (int i = 0; i < 16; i++) {
        v[i] = __half2float(row[tid + i * 256]);
        m = fmaxf(m, v[i]);
    }
#pragma unroll
    for (int o = 16; o; o >>= 1) m = fmaxf(m, __shfl_xor_sync(0xffffffffu, m, o));
    __shared__ float redm[8];
    __shared__ float reds[8];
    if ((tid & 31) == 0) redm[tid >> 5] = m;
    __syncthreads();
#pragma unroll
    for (int w = 0; w < 8; w++) m = fmaxf(m, redm[w]);
    float s = 0.f;
#pragma unroll
    for (int i = 0; i < 16; i++) {
        v[i] = expf(v[i] - m);
        s += v[i];
    }
#pragma unroll
    for (int o = 16; o; o >>= 1) s += __shfl_xor_sync(0xffffffffu, s, o);
    if ((tid & 31) == 0) reds[tid >> 5] = s;
    __syncthreads();
    s = 0.f;
#pragma unroll
    for (int w = 0; w < 8; w++) s += reds[w];
    float inv = 1.f / s;
#pragma unroll
    for (int i = 0; i < 16; i++)
        row[tid + i * 256] = __float2half(v[i] * inv);
}

// x_h[row][:768] = qin_h[row][:]   (uint4 = 8 halves per chunk)
__global__ __launch_bounds__(256) void concat_kernel(
    const __half* __restrict__ qh8, __half* __restrict__ x)
{
    const size_t Q8 = QD / 8;
    size_t idx = (size_t)blockIdx.x * blockDim.x + threadIdx.x;
    size_t rowi = idx / Q8;
    size_t c8 = idx % Q8;
    uint4 u = ((const uint4*)qh8)[idx];
    *(uint4*)(x + rowi * XD + c8 * 8) = u;
}

// ---------------------------------------------------------------------------
extern "C" void kernel_launch(void* const* d_in, const int* in_sizes, int n_in,
                              void* d_out, int out_size)
{
    const float* query = (const float*)d_in[0];
    const float* src   = (const float*)d_in[1];
    const float* trg   = (const float*)d_in[2];
    const float* Wq    = (const float*)d_in[3];
    const float* b_q   = (const float*)d_in[4];
    const float* Ws    = (const float*)d_in[5];
    const float* b_s   = (const float*)d_in[6];
    const float* Wt    = (const float*)d_in[7];
    const float* b_t   = (const float*)d_in[8];
    const float* Wo    = (const float*)d_in[9];
    const float* b_o   = (const float*)d_in[10];
    float* out = (float*)d_out;

    __half *qin_h, *st_h, *wqT, *wstT, *woT, *qh, *relh, *scoresh, *xh;
    float *stkey;
    cudaGetSymbolAddress((void**)&qin_h, g_qin_h);
    cudaGetSymbolAddress((void**)&st_h, g_st_h);
    cudaGetSymbolAddress((void**)&wqT, g_wqT);
    cudaGetSymbolAddress((void**)&wstT, g_wstT);
    cudaGetSymbolAddress((void**)&woT, g_woT);
    cudaGetSymbolAddress((void**)&qh, g_qh);
    cudaGetSymbolAddress((void**)&stkey, g_stkey);
    cudaGetSymbolAddress((void**)&relh, g_relh);
    cudaGetSymbolAddress((void**)&scoresh, g_scoresh);
    cudaGetSymbolAddress((void**)&xh, g_xh);

    const float inv_sqrt_h = 1.0f / sqrtf((float)HD);
    dim3 blk(256);

    cudaFuncSetAttribute(hgemm<true>,
                         cudaFuncAttributeMaxDynamicSharedMemorySize, SMEM_BYTES);
    cudaFuncSetAttribute(hgemm<false>,
                         cudaFuncAttributeMaxDynamicSharedMemorySize, SMEM_BYTES);

    // 0a. fused input conversion
    cvt_all_kernel<<<(unsigned)(CVT_TOT / 256), blk>>>(
        query, src, trg, qin_h, st_h);
    // 0b. fused weight transpose+convert
    transpose_all_kernel<<<dim3(HD / 32, XD / 32, 4), blk>>>(
        Wq, Ws, Wt, Wo, wqT, wstT, woT);

    // 1. q = query @ Wq + b_q  -> half
    hgemm<true><<<dim3(HD / 128, (BB * LL) / 128, 1), blk, SMEM_BYTES>>>(
        qin_h, QD, 0, wqT, QD, 0, b_q, nullptr, qh, HD, 0, QD, 1.f, 0, 1);

    // 2+3. [skey|tkey] = [src|trg] @ [Ws|Wt] + [b_s|b_t]  (z=2 merged)
    hgemm<true><<<dim3(HD / 128, (BB * SS) / 128, 2), blk, SMEM_BYTES>>>(
        st_h, FD, (size_t)BB * SS * FD,
        wstT, FD, (size_t)HD * FD,
        b_s, b_t,
        stkey, HD, (size_t)BB * SS * HD,
        FD, 1.f, 0, 0);

    // 4. rel = tanh.approx(half(skey + tkey))
    {
        size_t n4 = (size_t)BB * TSD * HD / 4;
        relkey_kernel<<<(unsigned)(n4 / 256), blk>>>(
            stkey, stkey + (size_t)BB * SS * HD, relh);
    }

    // 5. scores = q . rel^T / sqrt(H)  -> half   [NT]
    hgemm<true><<<dim3(TSD / 128, LL / 128, BB), blk, SMEM_BYTES>>>(
        qh, HD, (size_t)LL * HD,
        relh, HD, (size_t)TSD * HD,
        nullptr, nullptr,
        scoresh, TSD, (size_t)LL * TSD,
        HD, inv_sqrt_h, 0, 1);

    // 6. softmax in place on half
    softmax_kernel<<<BB * LL, blk>>>(scoresh);

    // 7. x_h[:, :768] = qin_h
    {
        size_t n8 = (size_t)BB * LL * QD / 8;
        concat_kernel<<<(unsigned)(n8 / 256), blk>>>(qin_h, xh);
    }

    // 8. x_h[:, 768:] = scores @ rel  -> half   [NN]
    hgemm<false><<<dim3(HD / 128, LL / 128, BB), blk, SMEM_BYTES>>>(
        scoresh, TSD, (size_t)LL * TSD,
        relh, HD, (size_t)TSD * HD,
        nullptr, nullptr,
        xh + QD, XD, (size_t)LL * XD,
        TSD, 1.f, 0, 1);

    // 9. out = relu(x @ Wo + b_o) -> fp32
    hgemm<true><<<dim3(OD / 128, (BB * LL) / 128, 1), blk, SMEM_BYTES>>>(
        xh, XD, 0, woT, XD, 0, b_o, nullptr, out, OD, 0, XD, 1.f, 1, 0);
}

// round 14
// speedup vs baseline: 3.0255x; 1.0411x over previous
#include <cuda_runtime.h>
#include <cuda_fp16.h>
#include <math.h>
#include <stdint.h>

// Problem dims
constexpr int BB = 32;
constexpr int LL = 256;
constexpr int SS = 64;
constexpr int TT = 64;
constexpr int QD = 768;
constexpr int FD = 1024;
constexpr int HD = 768;
constexpr int OD = 768;
constexpr int TSD = TT * SS;
constexpr int XD = QD + HD;

// Scratch (static device globals).
__device__ __align__(16) __half g_qin_h[(size_t)BB * LL * QD];
__device__ __align__(16) __half g_st_h[2 * (size_t)BB * SS * FD];   // [src|trg]
__device__ __align__(16) __half g_wqT[(size_t)HD * QD];             // [n][k]
__device__ __align__(16) __half g_wstT[2 * (size_t)HD * FD];        // [Ws|Wt] T
__device__ __align__(16) __half g_woT[(size_t)OD * XD];
__device__ __align__(16) __half g_qh[(size_t)BB * LL * HD];
__device__ __align__(16) float  g_stkey[2 * (size_t)BB * SS * HD];  // [skey|tkey]
__device__ __align__(16) __half g_relh[(size_t)BB * TSD * HD];      // [b][ts][h]
__device__ __align__(16) __half g_scoresh[(size_t)BB * LL * TSD];
__device__ __align__(16) __half g_xh[(size_t)BB * LL * XD];

__device__ __forceinline__ void cp16(uint32_t dst_smem, const void* src) {
    asm volatile("cp.async.cg.shared.global [%0], [%1], 16;\n"
                 :: "r"(dst_smem), "l"(src));
}
__device__ __forceinline__ void cp_commit() {
    asm volatile("cp.async.commit_group;\n");
}
template <int N>
__device__ __forceinline__ void cp_wait() {
    asm volatile("cp.async.wait_group %0;\n" :: "n"(N));
}

__device__ __forceinline__ void ldsm4(uint32_t* r, uint32_t addr) {
    asm volatile("ldmatrix.sync.aligned.m8n8.x4.shared.b16 {%0,%1,%2,%3}, [%4];"
                 : "=r"(r[0]), "=r"(r[1]), "=r"(r[2]), "=r"(r[3]) : "r"(addr));
}
__device__ __forceinline__ void ldsm4t(uint32_t* r, uint32_t addr) {
    asm volatile("ldmatrix.sync.aligned.m8n8.x4.trans.shared.b16 {%0,%1,%2,%3}, [%4];"
                 : "=r"(r[0]), "=r"(r[1]), "=r"(r[2]), "=r"(r[3]) : "r"(addr));
}

__device__ __forceinline__ void mma16(float* c, const uint32_t* a,
                                      uint32_t b0, uint32_t b1) {
    asm volatile(
        "mma.sync.aligned.m16n8k16.row.col.f32.f16.f16.f32 "
        "{%0,%1,%2,%3}, {%4,%5,%6,%7}, {%8,%9}, {%0,%1,%2,%3};"
        : "+f"(c[0]), "+f"(c[1]), "+f"(c[2]), "+f"(c[3])
        : "r"(a[0]), "r"(a[1]), "r"(a[2]), "r"(a[3]), "r"(b0), "r"(b1));
}

// ===========================================================================
// Shared GEMM body (EXACT R12 mainloop arithmetic, proven 621us).
// BK=64, 2-stage cp.async double buffer, one sync per iter.
// ===========================================================================
constexpr int NST  = 2;
constexpr int BK   = 64;
constexpr int HSTR = 72;
constexpr int HSTG = 128 * HSTR;
constexpr int BNNSTR = 136;
constexpr int BNNSTG = 64 * BNNSTR;
constexpr int SMEM_BYTES = NST * (HSTG + HSTG) * 2;   // 73728 B

template <bool NT>
__device__ __forceinline__ void hgemm_body(
    __half* smh,
    const __half* __restrict__ Ab, int lda,
    const __half* __restrict__ Bb, int ldb,
    const float* __restrict__ biasz,
    void* __restrict__ Cb, int ldc,
    int K, float scale, int do_relu, int out_half,
    int bm, int bn)
{
    __half* sA = smh;
    __half* sB = smh + NST * HSTG;
    constexpr int BSTG = NT ? HSTG : BNNSTG;

    const int tid  = threadIdx.x;
    const int lane = tid & 31;
    const int wid  = tid >> 5;
    const int wm   = wid & 1;
    const int wn   = wid >> 1;

    const uint32_t aU = (uint32_t)__cvta_generic_to_shared(sA);
    const uint32_t bU = (uint32_t)__cvta_generic_to_shared(sB);

    auto issue = [&](int st, int k0) {
        uint32_t ap = aU + (uint32_t)(st * HSTG * 2);
#pragma unroll
        for (int i = 0; i < 4; i++) {
            int c = tid + 256 * i;
            int r = c >> 3, col = (c & 7) * 8;
            cp16(ap + (r * HSTR + col) * 2, Ab + (size_t)(bm + r) * lda + k0 + col);
        }
        uint32_t bp = bU + (uint32_t)(st * BSTG * 2);
        if (NT) {
#pragma unroll
            for (int i = 0; i < 4; i++) {
                int c = tid + 256 * i;
                int r = c >> 3, col = (c & 7) * 8;
                cp16(bp + (r * HSTR + col) * 2, Bb + (size_t)(bn + r) * ldb + k0 + col);
            }
        } else {
#pragma unroll
            for (int i = 0; i < 4; i++) {
                int c = tid + 256 * i;
                int r = c >> 4, col = (c & 15) * 8;
                cp16(bp + (r * BNNSTR + col) * 2,
                     Bb + (size_t)(k0 + r) * ldb + bn + col);
            }
        }
    };

    float acc[4][4][4] = {};

    auto compute = [&](int st) {
        uint32_t aBase = aU + (uint32_t)(st * HSTG * 2);
        uint32_t bBase = bU + (uint32_t)(st * BSTG * 2);
        const int lrow = lane & 15;
        const int lhalf = lane >> 4;
#pragma unroll
        for (int ks = 0; ks < 4; ks++) {
            const int k0s = ks * 16;
            uint32_t a[4][4];
#pragma unroll
            for (int mt = 0; mt < 4; mt++) {
                int m0 = wm * 64 + mt * 16;
                ldsm4(a[mt], aBase + ((m0 + lrow) * HSTR + k0s + lhalf * 8) * 2);
            }
            uint32_t bf[2][4];
#pragma unroll
            for (int np = 0; np < 2; np++) {
                int n0 = wn * 32 + np * 16;
                if (NT) {
                    ldsm4(bf[np], bBase + ((n0 + lrow) * HSTR + k0s + lhalf * 8) * 2);
                } else {
                    ldsm4t(bf[np], bBase + ((k0s + lrow) * BNNSTR + n0 + lhalf * 8) * 2);
                }
            }
#pragma unroll
            for (int nt = 0; nt < 4; nt++) {
                uint32_t b0, b1;
                if (NT) {
                    b0 = bf[nt >> 1][nt & 1];
                    b1 = bf[nt >> 1][(nt & 1) + 2];
                } else {
                    b0 = bf[nt >> 1][(nt & 1) * 2];
                    b1 = bf[nt >> 1][(nt & 1) * 2 + 1];
                }
#pragma unroll
                for (int mt = 0; mt < 4; mt++)
                    mma16(acc[mt][nt], a[mt], b0, b1);
            }
        }
    };

    const int NI = K / BK;
    issue(0, 0); cp_commit();

    for (int it = 0; it < NI; it++) {
        cp_wait<0>();
        __syncthreads();
        if (it + 1 < NI) {
            issue((it + 1) & 1, (it + 1) * BK);
            cp_commit();
        }
        compute(it & 1);
    }

    // Epilogue
#pragma unroll
    for (int nt = 0; nt < 4; nt++) {
        int col = bn + wn * 32 + nt * 8 + (lane & 3) * 2;
        float bv0 = 0.f, bv1 = 0.f;
        if (biasz) { bv0 = biasz[col]; bv1 = biasz[col + 1]; }
#pragma unroll
        for (int mt = 0; mt < 4; mt++) {
            int r0 = bm + wm * 64 + mt * 16 + (lane >> 2);
            float v0 = acc[mt][nt][0] * scale + bv0;
            float v1 = acc[mt][nt][1] * scale + bv1;
            float v2 = acc[mt][nt][2] * scale + bv0;
            float v3 = acc[mt][nt][3] * scale + bv1;
            if (do_relu) {
                v0 = fmaxf(v0, 0.f); v1 = fmaxf(v1, 0.f);
                v2 = fmaxf(v2, 0.f); v3 = fmaxf(v3, 0.f);
            }
            if (out_half) {
                __half* C = (__half*)Cb;
                __half2 h0 = __floats2half2_rn(v0, v1);
                __half2 h1 = __floats2half2_rn(v2, v3);
                *(__half2*)(C + (size_t)r0 * ldc + col) = h0;
                *(__half2*)(C + (size_t)(r0 + 8) * ldc + col) = h1;
            } else {
                float* C = (float*)Cb;
                *(float2*)(C + (size_t)r0 * ldc + col) = make_float2(v0, v1);
                *(float2*)(C + (size_t)(r0 + 8) * ldc + col) = make_float2(v2, v3);
            }
        }
    }
}

// Generic GEMM kernel (batched over z).
template <bool NT>
__global__ __launch_bounds__(256) void hgemm(
    const __half* __restrict__ A, int lda, size_t sA_,
    const __half* __restrict__ B, int ldb, size_t sB_,
    const float* __restrict__ bias,
    void* __restrict__ Cv, int ldc, size_t sC_, int c_half_elts,
    int K, float scale, int do_relu, int out_half)
{
    extern __shared__ __half smh[];
    const __half* Ab = A + blockIdx.z * sA_;
    const __half* Bb = B + blockIdx.z * sB_;
    void* Cb = out_half
        ? (void*)((__half*)Cv + blockIdx.z * sC_)
        : (void*)((float*)Cv + blockIdx.z * sC_);
    hgemm_body<NT>(smh, Ab, lda, Bb, ldb, bias, Cb, ldc,
                   K, scale, do_relu, out_half,
                   blockIdx.y * 128, blockIdx.x * 128);
}

// Fused q/s/t projection kernel: grid (6, 64, 3).
//  z=0: q = qin_h @ wqT + b_q   (K=QD, 64 y-blocks, half out)
//  z=1: skey = src @ wsT + b_s  (K=FD, 16 y-blocks, fp32 out)
//  z=2: tkey = trg @ wtT + b_t  (K=FD, 16 y-blocks, fp32 out)
__global__ __launch_bounds__(256) void proj_fused_kernel(
    const __half* __restrict__ qin_h, const __half* __restrict__ st_h,
    const __half* __restrict__ wqT, const __half* __restrict__ wstT,
    const float* __restrict__ b_q, const float* __restrict__ b_s,
    const float* __restrict__ b_t,
    __half* __restrict__ qh, float* __restrict__ stkey)
{
    extern __shared__ __half smh[];
    const int z = blockIdx.z;
    if (z > 0 && blockIdx.y >= (BB * SS) / 128) return;
    const __half* Ab;
    const __half* Bb;
    const float* bias;
    void* Cb;
    int lda, K, out_half;
    if (z == 0) {
        Ab = qin_h; lda = QD; Bb = wqT; bias = b_q;
        Cb = qh; K = QD; out_half = 1;
    } else {
        size_t off = (size_t)(z - 1);
        Ab = st_h + off * ((size_t)BB * SS * FD); lda = FD;
        Bb = wstT + off * ((size_t)HD * FD);
        bias = (z == 1) ? b_s : b_t;
        Cb = stkey + off * ((size_t)BB * SS * HD);
        K = FD; out_half = 0;
    }
    hgemm_body<true>(smh, Ab, lda, Bb, lda, bias, Cb, HD,
                     K, 1.f, 0, out_half,
                     blockIdx.y * 128, blockIdx.x * 128);
}

// ---------------------------------------------------------------------------
// Fused prep: fp32 -> half for query, src, trg in ONE launch.
constexpr size_t CVT_C1 = (size_t)BB * LL * QD / 4;
constexpr size_t CVT_C2 = (size_t)BB * SS * FD / 4;
constexpr size_t CVT_TOT = CVT_C1 + 2 * CVT_C2;

__global__ __launch_bounds__(256) void cvt_all_kernel(
    const float* __restrict__ query, const float* __restrict__ src,
    const float* __restrict__ trg,
    __half* __restrict__ qin_h, __half* __restrict__ st_h)
{
    size_t i = (size_t)blockIdx.x * blockDim.x + threadIdx.x;
    const float* sp;
    __half* dp;
    size_t off;
    if (i < CVT_C1)            { sp = query; dp = qin_h; off = i; }
    else if (i < CVT_C1 + CVT_C2) { sp = src; dp = st_h; off = i - CVT_C1; }
    else                       { sp = trg; dp = st_h + (size_t)BB * SS * FD;
                                 off = i - CVT_C1 - CVT_C2; }
    float4 v = ((const float4*)sp)[off];
    __half2 a = __floats2half2_rn(v.x, v.y);
    __half2 b = __floats2half2_rn(v.z, v.w);
    uint2 u;
    u.x = *(uint32_t*)&a; u.y = *(uint32_t*)&b;
    ((uint2*)dp)[off] = u;
}

// Fused transpose+convert for all 4 weights.
__global__ __launch_bounds__(256) void transpose_all_kernel(
    const float* __restrict__ Wq, const float* __restrict__ Ws,
    const float* __restrict__ Wt, const float* __restrict__ Wo,
    __half* __restrict__ wqT, __half* __restrict__ wstT,
    __half* __restrict__ woT)
{
    const int z = blockIdx.z;
    int Kd;
    const float* W;
    __half* WT;
    if (z == 0)      { Kd = QD; W = Wq; WT = wqT; }
    else if (z == 1) { Kd = FD; W = Ws; WT = wstT; }
    else if (z == 2) { Kd = FD; W = Wt; WT = wstT + (size_t)HD * FD; }
    else             { Kd = XD; W = Wo; WT = woT; }
    const int k0 = blockIdx.y * 32;
    if (k0 >= Kd) return;
    const int Nd = HD;
    __shared__ float t[32][33];
    const int tx = threadIdx.x & 31, ty = threadIdx.x >> 5;
    const int n0 = blockIdx.x * 32;
#pragma unroll
    for (int i = 0; i < 4; i++)
        t[ty + 8 * i][tx] = W[(size_t)(k0 + ty + 8 * i) * Nd + n0 + tx];
    __syncthreads();
#pragma unroll
    for (int i = 0; i < 4; i++)
        WT[(size_t)(n0 + ty + 8 * i) * Kd + k0 + tx] = __float2half(t[tx][ty + 8 * i]);
}

// rel = tanh.approx.f16x2(half2(skey + tkey)); 8 halves (16B) per thread.
__global__ __launch_bounds__(256) void relkey_kernel(
    const float* __restrict__ skey, const float* __restrict__ tkey,
    __half* __restrict__ rel)
{
    const size_t H8 = HD / 8;
    size_t idx = (size_t)blockIdx.x * blockDim.x + threadIdx.x;
    size_t h8 = idx % H8;
    size_t rest = idx / H8;
    int s = (int)(rest % SS); rest /= SS;
    int t = (int)(rest % TT);
    int b = (int)(rest / TT);
    const float4* sp = (const float4*)(skey + ((size_t)b * SS + s) * HD) + h8 * 2;
    const float4* tp = (const float4*)(tkey + ((size_t)b * TT + t) * HD) + h8 * 2;
    float4 sv0 = sp[0], sv1 = sp[1];
    float4 tv0 = tp[0], tv1 = tp[1];
    __half2 x0 = __floats2half2_rn(sv0.x + tv0.x, sv0.y + tv0.y);
    __half2 x1 = __floats2half2_rn(sv0.z + tv0.z, sv0.w + tv0.w);
    __half2 x2 = __floats2half2_rn(sv1.x + tv1.x, sv1.y + tv1.y);
    __half2 x3 = __floats2half2_rn(sv1.z + tv1.z, sv1.w + tv1.w);
    uint4 u;
    asm("tanh.approx.f16x2 %0, %1;" : "=r"(u.x) : "r"(*(uint32_t*)&x0));
    asm("tanh.approx.f16x2 %0, %1;" : "=r"(u.y) : "r"(*(uint32_t*)&x1));
    asm("tanh.approx.f16x2 %0, %1;" : "=r"(u.z) : "r"(*(uint32_t*)&x2));
    asm("tanh.approx.f16x2 %0, %1;" : "=r"(u.w) : "r"(*(uint32_t*)&x3));
    ((uint4*)rel)[idx] = u;
}

// Softmax over 4096 per row: half in/out, in place. Math in fp32.
__global__ __launch_bounds__(256) void softmax_kernel(__half* __restrict__ data)
{
    __half* row = data + (size_t)blockIdx.x * TSD;
    const int tid = threadIdx.x;
    float v[16];
    float m = -INFINITY;
#pragma unroll
    for (int i = 0; i < 16; i++) {
        v[i] = __half2float(row[tid + i * 256]);
        m = fmaxf(m, v[i]);
    }
#pragma unroll
    for (int o = 16; o; o >>= 1) m = fmaxf(m, __shfl_xor_sync(0xffffffffu, m, o));
    __shared__ float redm[8];
    __shared__ float reds[8];
    if ((tid & 31) == 0) redm[tid >> 5] = m;
    __syncthreads();
#pragma unroll
    for (int w = 0; w < 8; w++) m = fmaxf(m, redm[w]);
    float s = 0.f;
#pragma unroll
    for (int i = 0; i < 16; i++) {
        v[i] = expf(v[i] - m);
        s += v[i];
    }
#pragma unroll
    for (int o = 16; o; o >>= 1) s += __shfl_xor_sync(0xffffffffu, s, o);
    if ((tid & 31) == 0) reds[tid >> 5] = s;
    __syncthreads();
    s = 0.f;
#pragma unroll
    for (int w = 0; w < 8; w++) s += reds[w];
    float inv = 1.f / s;
#pragma unroll
    for (int i = 0; i < 16; i++)
        row[tid + i * 256] = __float2half(v[i] * inv);
}

// x_h[row][:768] = qin_h[row][:]
__global__ __launch_bounds__(256) void concat_kernel(
    const __half* __restrict__ qh8, __half* __restrict__ x)
{
    const size_t Q8 = QD / 8;
    size_t idx = (size_t)blockIdx.x * blockDim.x + threadIdx.x;
    size_t rowi = idx / Q8;
    size_t c8 = idx % Q8;
    uint4 u = ((const uint4*)qh8)[idx];
    *(uint4*)(x + rowi * XD + c8 * 8) = u;
}

// ---------------------------------------------------------------------------
extern "C" void kernel_launch(void* const* d_in, const int* in_sizes, int n_in,
                              void* d_out, int out_size)
{
    const float* query = (const float*)d_in[0];
    const float* src   = (const float*)d_in[1];
    const float* trg   = (const float*)d_in[2];
    const float* Wq    = (const float*)d_in[3];
    const float* b_q   = (const float*)d_in[4];
    const float* Ws    = (const float*)d_in[5];
    const float* b_s   = (const float*)d_in[6];
    const float* Wt    = (const float*)d_in[7];
    const float* b_t   = (const float*)d_in[8];
    const float* Wo    = (const float*)d_in[9];
    const float* b_o   = (const float*)d_in[10];
    float* out = (float*)d_out;

    __half *qin_h, *st_h, *wqT, *wstT, *woT, *qh, *relh, *scoresh, *xh;
    float *stkey;
    cudaGetSymbolAddress((void**)&qin_h, g_qin_h);
    cudaGetSymbolAddress((void**)&st_h, g_st_h);
    cudaGetSymbolAddress((void**)&wqT, g_wqT);
    cudaGetSymbolAddress((void**)&wstT, g_wstT);
    cudaGetSymbolAddress((void**)&woT, g_woT);
    cudaGetSymbolAddress((void**)&qh, g_qh);
    cudaGetSymbolAddress((void**)&stkey, g_stkey);
    cudaGetSymbolAddress((void**)&relh, g_relh);
    cudaGetSymbolAddress((void**)&scoresh, g_scoresh);
    cudaGetSymbolAddress((void**)&xh, g_xh);

    const float inv_sqrt_h = 1.0f / sqrtf((float)HD);
    dim3 blk(256);

    cudaFuncSetAttribute(hgemm<true>,
                         cudaFuncAttributeMaxDynamicSharedMemorySize, SMEM_BYTES);
    cudaFuncSetAttribute(hgemm<false>,
                         cudaFuncAttributeMaxDynamicSharedMemorySize, SMEM_BYTES);
    cudaFuncSetAttribute(proj_fused_kernel,
                         cudaFuncAttributeMaxDynamicSharedMemorySize, SMEM_BYTES);

    // 0a. fused input conversion
    cvt_all_kernel<<<(unsigned)(CVT_TOT / 256), blk>>>(
        query, src, trg, qin_h, st_h);
    // 0b. fused weight transpose+convert
    transpose_all_kernel<<<dim3(HD / 32, XD / 32, 4), blk>>>(
        Wq, Ws, Wt, Wo, wqT, wstT, woT);

    // 1+2+3. fused projections (q, skey, tkey) in one launch
    proj_fused_kernel<<<dim3(HD / 128, (BB * LL) / 128, 3), blk, SMEM_BYTES>>>(
        qin_h, st_h, wqT, wstT, b_q, b_s, b_t, qh, stkey);

    // 4. rel = tanh.approx(half(skey + tkey))
    {
        size_t n8 = (size_t)BB * TSD * HD / 8;
        relkey_kernel<<<(unsigned)(n8 / 256), blk>>>(
            stkey, stkey + (size_t)BB * SS * HD, relh);
    }

    // 5. scores = q . rel^T / sqrt(H)  -> half   [NT]
    hgemm<true><<<dim3(TSD / 128, LL / 128, BB), blk, SMEM_BYTES>>>(
        qh, HD, (size_t)LL * HD,
        relh, HD, (size_t)TSD * HD,
        nullptr,
        scoresh, TSD, (size_t)LL * TSD, 1,
        HD, inv_sqrt_h, 0, 1);

    // 6. softmax in place on half
    softmax_kernel<<<BB * LL, blk>>>(scoresh);

    // 7. x_h[:, :768] = qin_h
    {
        size_t n8 = (size_t)BB * LL * QD / 8;
        concat_kernel<<<(unsigned)(n8 / 256), blk>>>(qin_h, xh);
    }

    // 8. x_h[:, 768:] = scores @ rel  -> half   [NN]
    hgemm<false><<<dim3(HD / 128, LL / 128, BB), blk, SMEM_BYTES>>>(
        scoresh, TSD, (size_t)LL * TSD,
        relh, HD, (size_t)TSD * HD,
        nullptr,
        xh + QD, XD, (size_t)LL * XD, 1,
        TSD, 1.f, 0, 1);

    // 9. out = relu(x @ Wo + b_o) -> fp32
    hgemm<true><<<dim3(OD / 128, (BB * LL) / 128, 1), blk, SMEM_BYTES>>>(
        xh, XD, 0, woT, XD, 0, b_o, out, OD, 0, 0, XD, 1.f, 1, 0);
}